// round 2
// baseline (speedup 1.0000x reference)
#include <cuda_runtime.h>
#include <math.h>
#include <stdint.h>

#define Bsz 64
#define Dd  768
#define VOC 100000
#define KTOP 512

// ---------- scratch ----------
__device__ float g_x [Bsz*3072];
__device__ float g_h1[Bsz*2304];
__device__ float g_h2[Bsz*1700];
__device__ float g_h3[Bsz*1000];
__device__ float g_h4[Bsz*768];
__device__ float g_mo[Bsz*768];
__device__ float g_cluet[Bsz*768*32];          // normalized clues, [b][d][c] c<25
__device__ float g_sims[(size_t)Bsz*VOC];
__device__ int   g_topidx[Bsz*KTOP];
__device__ float g_tot[Bsz*KTOP];
__device__ int   g_flags[Bsz*KTOP];
__device__ int   g_search[Bsz];
__device__ float g_part[884736];

__device__ __forceinline__ unsigned f2u(float f){
    unsigned u = __float_as_uint(f);
    return (u & 0x80000000u) ? ~u : (u | 0x80000000u);
}

// ---------- stage 1: pooled concat x = [pool(neg)|assas|pool(neut)|pool(pos)]
__global__ void pool_concat_k(const float* __restrict__ pos, const float* __restrict__ neg,
                              const float* __restrict__ neut, const float* __restrict__ assas){
    int b=blockIdx.y, g=blockIdx.x, t=threadIdx.x;
    __shared__ float red[256];
    const float* src; int n, xoff;
    if(g==0){src=neg +(size_t)b*8*Dd; n=8; xoff=0;}
    else if(g==1){src=assas+(size_t)b*Dd; n=1; xoff=Dd;}
    else if(g==2){src=neut+(size_t)b*7*Dd; n=7; xoff=2*Dd;}
    else {src=pos +(size_t)b*9*Dd; n=9; xoff=3*Dd;}
    float m[3];
#pragma unroll
    for(int i=0;i<3;i++){int d=t+i*256; float s=0.f;
        for(int j=0;j<n;j++) s+=src[(size_t)j*Dd+d]; m[i]=s/(float)n;}
    if(g==1){
#pragma unroll
        for(int i=0;i<3;i++) g_x[b*3072+xoff+t+i*256]=m[i];
        return;
    }
    red[t]=m[0]*m[0]+m[1]*m[1]+m[2]*m[2]; __syncthreads();
    for(int s=128;s>0;s>>=1){ if(t<s) red[t]+=red[t+s]; __syncthreads(); }
    float inv=1.f/fmaxf(sqrtf(red[0]),1e-12f);
#pragma unroll
    for(int i=0;i<3;i++) g_x[b*3072+xoff+t+i*256]=m[i]*inv;
}

// ---------- stage 1b: normalized clue table, transposed: g_cluet[b][d][c], c: pos9,neg8,neut7,assas1
__global__ void clue_norm_k(const float* __restrict__ pos, const float* __restrict__ neg,
                            const float* __restrict__ neut, const float* __restrict__ assas){
    int c=blockIdx.x, b=blockIdx.y, t=threadIdx.x;
    const float* src;
    if(c<9)       src=pos +((size_t)b*9+c)*Dd;
    else if(c<17) src=neg +((size_t)b*8+(c-9))*Dd;
    else if(c<24) src=neut+((size_t)b*7+(c-17))*Dd;
    else          src=assas+(size_t)b*Dd;
    __shared__ float red[256];
    float m[3]; float loc=0.f;
#pragma unroll
    for(int i=0;i<3;i++){ m[i]=src[t+i*256]; loc+=m[i]*m[i]; }
    red[t]=loc; __syncthreads();
    for(int s=128;s>0;s>>=1){ if(t<s) red[t]+=red[t+s]; __syncthreads(); }
    float inv=1.f/fmaxf(sqrtf(red[0]),1e-12f);
#pragma unroll
    for(int i=0;i<3;i++) g_cluet[((size_t)b*768+t+i*256)*32+c]=m[i]*inv;
}

// ---------- MLP GEMM: 64 rows, tile 64x32, K-split partials ----------
__global__ void gemm64_k(const float* __restrict__ X, const float* __restrict__ W,
                         float* __restrict__ part, int Kdim, int Ndim, int kchunk){
    __shared__ float xs[32][64];
    __shared__ float ws[32][32];
    int tid=threadIdx.x;            // 128
    int n0=blockIdx.x*32;
    int kbeg=blockIdx.y*kchunk, kend=min(Kdim,kbeg+kchunk);
    int rg=tid&15, cg=tid>>4;
    float acc[4][4];
#pragma unroll
    for(int i=0;i<4;i++)
#pragma unroll
        for(int j=0;j<4;j++) acc[i][j]=0.f;
    for(int k0=kbeg;k0<kend;k0+=32){
#pragma unroll
        for(int i=0;i<4;i++){
            int q=tid+i*128, r=q>>3, c4=(q&7)*4, k=k0+c4;
            float4 v=make_float4(0,0,0,0);
            if(k<kend) v=*(const float4*)(X+(size_t)r*Kdim+k);
            xs[c4+0][r]=v.x; xs[c4+1][r]=v.y; xs[c4+2][r]=v.z; xs[c4+3][r]=v.w;
        }
#pragma unroll
        for(int i=0;i<2;i++){
            int q=tid+i*128, r=q>>3, c4=(q&7)*4, k=k0+r, n=n0+c4;
            float4 v=make_float4(0,0,0,0);
            if(k<kend && n<Ndim) v=*(const float4*)(W+(size_t)k*Ndim+n);
            ws[r][c4+0]=v.x; ws[r][c4+1]=v.y; ws[r][c4+2]=v.z; ws[r][c4+3]=v.w;
        }
        __syncthreads();
#pragma unroll
        for(int kk=0;kk<32;kk++){
            float4 a=*(const float4*)&xs[kk][rg*4];
            float4 bv=*(const float4*)&ws[kk][cg*4];
            float av[4]={a.x,a.y,a.z,a.w}, bb[4]={bv.x,bv.y,bv.z,bv.w};
#pragma unroll
            for(int i=0;i<4;i++)
#pragma unroll
                for(int j=0;j<4;j++) acc[i][j]+=av[i]*bb[j];
        }
        __syncthreads();
    }
    float* dst=part+(size_t)blockIdx.y*Bsz*Ndim;
#pragma unroll
    for(int i=0;i<4;i++)
#pragma unroll
        for(int j=0;j<4;j++){
            int col=n0+cg*4+j;
            if(col<Ndim) dst[(size_t)(rg*4+i)*Ndim+col]=acc[i][j];
        }
}

__global__ void combine_act_k(const float* __restrict__ part, const float* __restrict__ bias,
                              float* __restrict__ Y, int Ndim, int S, int act){
    int idx=blockIdx.x*blockDim.x+threadIdx.x;
    int total=Bsz*Ndim;
    if(idx>=total) return;
    int c=idx%Ndim;
    float s=bias[c];
    for(int sp=0;sp<S;sp++) s+=part[(size_t)sp*total+idx];
    Y[idx]=act?tanhf(s):s;
}

__global__ void norm_mo_k(float* __restrict__ out){
    int b=blockIdx.x, t=threadIdx.x;
    __shared__ float red[256];
    float m[3]; float loc=0.f;
#pragma unroll
    for(int i=0;i<3;i++){ m[i]=g_h4[b*768+t+i*256]; loc+=m[i]*m[i]; }
    red[t]=loc; __syncthreads();
    for(int s=128;s>0;s>>=1){ if(t<s) red[t]+=red[t+s]; __syncthreads(); }
    float inv=1.f/fmaxf(sqrtf(red[0]),1e-12f);
#pragma unroll
    for(int i=0;i<3;i++){
        float v=m[i]*inv;
        g_mo[b*768+t+i*256]=v;
        out[b*768+t+i*256]=v;
    }
}

// ---------- sims = mo . vocab_row / ||row||, tile 128 vocab x 64 batch ----------
__global__ void sims_k(const float* __restrict__ vocab){
    __shared__ float vs[16][128];
    __shared__ float ms[16][64];
    __shared__ float rinv[128];
    int tid=threadIdx.x;            // 256
    int v0=blockIdx.x*128;
    int rg=tid&15, cg=tid>>4;       // 8 rows x 4 cols per thread
    float acc[8][4];
#pragma unroll
    for(int i=0;i<8;i++)
#pragma unroll
        for(int j=0;j<4;j++) acc[i][j]=0.f;
    float sq0=0.f, sq1=0.f;
    for(int k0=0;k0<768;k0+=16){
#pragma unroll
        for(int i=0;i<2;i++){
            int q=tid+i*256, r=q>>2, c4=(q&3)*4, gr=v0+r;
            float4 v=make_float4(0,0,0,0);
            if(gr<VOC) v=*(const float4*)(vocab+(size_t)gr*768+k0+c4);
            vs[c4+0][r]=v.x; vs[c4+1][r]=v.y; vs[c4+2][r]=v.z; vs[c4+3][r]=v.w;
            float s=v.x*v.x+v.y*v.y+v.z*v.z+v.w*v.w;
            if(i==0) sq0+=s; else sq1+=s;
        }
        {
            int q=tid, bcol=q>>2, c4=(q&3)*4;
            float4 v=*(const float4*)(g_mo+(size_t)bcol*768+k0+c4);
            ms[c4+0][bcol]=v.x; ms[c4+1][bcol]=v.y; ms[c4+2][bcol]=v.z; ms[c4+3][bcol]=v.w;
        }
        __syncthreads();
#pragma unroll
        for(int kk=0;kk<16;kk++){
            float4 a0=*(const float4*)&vs[kk][rg*8];
            float4 a1=*(const float4*)&vs[kk][rg*8+4];
            float4 b4=*(const float4*)&ms[kk][cg*4];
            float av[8]={a0.x,a0.y,a0.z,a0.w,a1.x,a1.y,a1.z,a1.w};
            float bb[4]={b4.x,b4.y,b4.z,b4.w};
#pragma unroll
            for(int i=0;i<8;i++)
#pragma unroll
                for(int j=0;j<4;j++) acc[i][j]+=av[i]*bb[j];
        }
        __syncthreads();
    }
    // row sumsq reduce among quads (lanes 4k..4k+3 share a row)
    sq0+=__shfl_xor_sync(0xffffffff,sq0,1); sq0+=__shfl_xor_sync(0xffffffff,sq0,2);
    sq1+=__shfl_xor_sync(0xffffffff,sq1,1); sq1+=__shfl_xor_sync(0xffffffff,sq1,2);
    if((tid&3)==0){
        rinv[tid>>2]     =1.f/fmaxf(sqrtf(sq0),1e-12f);
        rinv[64+(tid>>2)]=1.f/fmaxf(sqrtf(sq1),1e-12f);
    }
    __syncthreads();
#pragma unroll
    for(int j=0;j<4;j++){
        int bcol=cg*4+j;
#pragma unroll
        for(int i=0;i<8;i++){
            int vr=v0+rg*8+i;
            if(vr<VOC) g_sims[(size_t)bcol*VOC+vr]=acc[i][j]*rinv[rg*8+i];
        }
    }
}

// ---------- exact top-512 per batch: radix select + stable tie handling + bitonic ----------
__global__ void topk_k(){
    int b=blockIdx.x, t=threadIdx.x;   // 512 threads
    __shared__ unsigned hist[256];
    __shared__ unsigned sh_prefix, sh_need, sh_cgt;
    __shared__ unsigned long long keys[512];
    __shared__ unsigned eqidx[1024];
    __shared__ unsigned ctr_gt, ctr_eq;
    const float* srow=g_sims+(size_t)b*VOC;
    unsigned prefix=0, need=512, cgt=0;
    for(int shift=24;shift>=0;shift-=8){
        for(int i=t;i<256;i+=512) hist[i]=0;
        __syncthreads();
        for(int v=t;v<VOC;v+=512){
            unsigned u=f2u(srow[v]);
            if(shift==24 || (u>>(shift+8))==prefix)
                atomicAdd(&hist[(u>>shift)&255],1u);
        }
        __syncthreads();
        if(t==0){
            unsigned acc=0; int bin=255;
            for(;bin>0;bin--){ if(acc+hist[bin]>=need) break; acc+=hist[bin]; }
            sh_prefix=(prefix<<8)|(unsigned)bin;
            sh_need=need-acc;
            sh_cgt=cgt+acc;
        }
        __syncthreads();
        prefix=sh_prefix; need=sh_need; cgt=sh_cgt;
        __syncthreads();
    }
    unsigned thr=prefix;
    if(t==0){ ctr_gt=0; ctr_eq=0; }
    __syncthreads();
    for(int v=t;v<VOC;v+=512){
        unsigned u=f2u(srow[v]);
        if(u>thr){
            unsigned p=atomicAdd(&ctr_gt,1u);
            keys[p]=((unsigned long long)(~u)<<32)|(unsigned)v;
        } else if(u==thr){
            unsigned p=atomicAdd(&ctr_eq,1u);
            if(p<1024) eqidx[p]=(unsigned)v;
        }
    }
    __syncthreads();
    int ne=min(ctr_eq,1024u);
    for(int i=t;i<ne;i+=512){
        unsigned myv=eqidx[i]; int rank=0;
        for(int j=0;j<ne;j++) rank+=(eqidx[j]<myv);
        if(rank<(int)need) keys[cgt+rank]=((unsigned long long)(~thr)<<32)|myv;
    }
    __syncthreads();
    // bitonic ascending on keys (~u,idx)  => sim desc, idx asc
    for(unsigned k=2;k<=512;k<<=1){
        for(unsigned j=k>>1;j>0;j>>=1){
            unsigned ixj=t^j;
            if(ixj>(unsigned)t){
                unsigned long long a=keys[t], c=keys[ixj];
                bool up=((t&k)==0);
                if((a>c)==up){ keys[t]=c; keys[ixj]=a; }
            }
            __syncthreads();
        }
    }
    g_topidx[b*512+t]=(int)(keys[t]&0xffffffffu);
}

// ---------- gathered clue GEMM + primary/secondary (scale-invariant, skip wn norm) ----------
__global__ void combined_k(const float* __restrict__ vocab){
    __shared__ float ws[32][64];
    __shared__ float cs[32][32];
    __shared__ int sidx[64];
    __shared__ float outc[64][32];
    int b=blockIdx.y, w0=blockIdx.x*64, tid=threadIdx.x; // 256
    if(tid<64) sidx[tid]=g_topidx[b*512+w0+tid];
    __syncthreads();
    int c=tid&31, w8=tid>>5;
    float acc[8];
#pragma unroll
    for(int i=0;i<8;i++) acc[i]=0.f;
    for(int k0=0;k0<768;k0+=32){
#pragma unroll
        for(int i=0;i<2;i++){
            int q=tid+i*256, r=q>>3, c4=(q&7)*4;
            float4 v=*(const float4*)(vocab+(size_t)sidx[r]*768+k0+c4);
            ws[c4+0][r]=v.x; ws[c4+1][r]=v.y; ws[c4+2][r]=v.z; ws[c4+3][r]=v.w;
        }
#pragma unroll
        for(int i=0;i<4;i++){
            int q=tid+i*256, kk=q>>5, cc=q&31;
            cs[kk][cc]=(cc<25)?g_cluet[((size_t)b*768+k0+kk)*32+cc]:0.f;
        }
        __syncthreads();
#pragma unroll
        for(int kk=0;kk<32;kk++){
            float cv=cs[kk][c];
            float4 a0=*(const float4*)&ws[kk][w8*8];
            float4 a1=*(const float4*)&ws[kk][w8*8+4];
            acc[0]+=a0.x*cv; acc[1]+=a0.y*cv; acc[2]+=a0.z*cv; acc[3]+=a0.w*cv;
            acc[4]+=a1.x*cv; acc[5]+=a1.y*cv; acc[6]+=a1.z*cv; acc[7]+=a1.w*cv;
        }
        __syncthreads();
    }
#pragma unroll
    for(int i=0;i<8;i++) outc[w8*8+i][c]=acc[i];
    __syncthreads();
    if(tid<64){
        float* row=outc[tid];
        float mbest=-1e30f; int jbest=9;
        for(int j=9;j<25;j++){ float v=row[j]; if(v>mbest){mbest=v; jbest=j;} }
        int primary=0;
        for(int p=0;p<9;p++) primary+=(row[p]>=mbest);
        float sec=(jbest<17)?0.f:((jbest<24)?1.f:-10.f);
        g_tot[b*512+w0+tid]=(float)primary+sec;
    }
}

// ---------- rank with exact jax top_k tie semantics on tot_reward ----------
__global__ void rank_k(){
    int b=blockIdx.x, t=threadIdx.x; // 512
    __shared__ float tv[512];
    tv[t]=g_tot[b*512+t]; __syncthreads();
    float mv=tv[t]; int gt=0, lt=0, eqb=0;
    for(int j=0;j<512;j++){
        float o=tv[j];
        gt+=(o>mv); lt+=(o<mv); eqb+=((o==mv)&&(j<t));
    }
    int rmax=gt+eqb, rmin=lt+eqb;
    g_flags[b*512+t]=((rmax<256)?1:0)|((rmin<256)?2:0);
    if(rmax==0) g_search[b]=g_topidx[b*512+t];
}

// ---------- final: pooled max/min + search embedding ----------
__global__ void final_k(const float* __restrict__ vocab, float* __restrict__ out){
    int b=blockIdx.x, t=threadIdx.x; // 256
    __shared__ float red[256];
    float amax[3]={0,0,0}, amin[3]={0,0,0};
    const int* ti=g_topidx+b*512;
    const int* fl=g_flags+b*512;
    for(int w=0;w<512;w++){
        int f=fl[w];
        if(f){
            const float* row=vocab+(size_t)ti[w]*768;
#pragma unroll
            for(int i=0;i<3;i++){
                float v=row[t+i*256];
                if(f&1) amax[i]+=v;
                if(f&2) amin[i]+=v;
            }
        }
    }
    // max_pooled
    float loc=0.f;
#pragma unroll
    for(int i=0;i<3;i++){ amax[i]*=(1.f/256.f); loc+=amax[i]*amax[i]; }
    red[t]=loc; __syncthreads();
    for(int s=128;s>0;s>>=1){ if(t<s) red[t]+=red[t+s]; __syncthreads(); }
    float inv=1.f/fmaxf(sqrtf(red[0]),1e-12f);
#pragma unroll
    for(int i=0;i<3;i++) out[2*49152+b*768+t+i*256]=amax[i]*inv;
    __syncthreads();
    // min_pooled
    loc=0.f;
#pragma unroll
    for(int i=0;i<3;i++){ amin[i]*=(1.f/256.f); loc+=amin[i]*amin[i]; }
    red[t]=loc; __syncthreads();
    for(int s=128;s>0;s>>=1){ if(t<s) red[t]+=red[t+s]; __syncthreads(); }
    inv=1.f/fmaxf(sqrtf(red[0]),1e-12f);
#pragma unroll
    for(int i=0;i<3;i++) out[3*49152+b*768+t+i*256]=amin[i]*inv;
    // search embedding (raw vocab row)
    int sw=g_search[b];
#pragma unroll
    for(int i=0;i<3;i++) out[49152+b*768+t+i*256]=vocab[(size_t)sw*768+t+i*256];
}

extern "C" void kernel_launch(void* const* d_in, const int* in_sizes, int n_in,
                              void* d_out, int out_size){
    const float* pos  =(const float*)d_in[0];
    const float* neg  =(const float*)d_in[1];
    const float* neut =(const float*)d_in[2];
    const float* assas=(const float*)d_in[3];
    const float* vocab=(const float*)d_in[4];
    const float* W1=(const float*)d_in[5];  const float* b1=(const float*)d_in[6];
    const float* W2=(const float*)d_in[7];  const float* b2=(const float*)d_in[8];
    const float* W3=(const float*)d_in[9];  const float* b3=(const float*)d_in[10];
    const float* W4=(const float*)d_in[11]; const float* b4=(const float*)d_in[12];
    float* out=(float*)d_out;

    float *gx, *gh1, *gh2, *gh3, *gh4, *gpart;
    cudaGetSymbolAddress((void**)&gx,   g_x);
    cudaGetSymbolAddress((void**)&gh1,  g_h1);
    cudaGetSymbolAddress((void**)&gh2,  g_h2);
    cudaGetSymbolAddress((void**)&gh3,  g_h3);
    cudaGetSymbolAddress((void**)&gh4,  g_h4);
    cudaGetSymbolAddress((void**)&gpart,g_part);

    pool_concat_k<<<dim3(4,64),256>>>(pos,neg,neut,assas);
    clue_norm_k<<<dim3(25,64),256>>>(pos,neg,neut,assas);

    // L1: 3072->2304
    gemm64_k<<<dim3(72,2),128>>>(gx,W1,gpart,3072,2304,1536);
    combine_act_k<<<(64*2304+255)/256,256>>>(gpart,b1,gh1,2304,2,1);
    // L2: 2304->1700
    gemm64_k<<<dim3(54,3),128>>>(gh1,W2,gpart,2304,1700,768);
    combine_act_k<<<(64*1700+255)/256,256>>>(gpart,b2,gh2,1700,3,1);
    // L3: 1700->1000
    gemm64_k<<<dim3(32,5),128>>>(gh2,W3,gpart,1700,1000,352);
    combine_act_k<<<(64*1000+255)/256,256>>>(gpart,b3,gh3,1000,5,1);
    // L4: 1000->768 (no tanh)
    gemm64_k<<<dim3(24,6),128>>>(gh3,W4,gpart,1000,768,192);
    combine_act_k<<<(64*768+255)/256,256>>>(gpart,b4,gh4,768,6,0);

    norm_mo_k<<<64,256>>>(out);
    sims_k<<<(VOC+127)/128,256>>>(vocab);
    topk_k<<<64,512>>>();
    combined_k<<<dim3(8,64),256>>>(vocab);
    rank_k<<<64,512>>>();
    final_k<<<64,256>>>(vocab,out);
}

// round 3
// speedup vs baseline: 1.0986x; 1.0986x over previous
#include <cuda_runtime.h>
#include <math.h>
#include <stdint.h>

#define Bsz 64
#define Dd  768
#define VOC 100000
#define KTOP 512

typedef unsigned long long u64t;

// ---------- scratch ----------
__device__ float g_x [Bsz*3072];
__device__ float g_h1[Bsz*2304];
__device__ float g_h2[Bsz*1700];
__device__ float g_h3[Bsz*1000];
__device__ float g_h4[Bsz*768];
__device__ float g_mo[Bsz*768];
__device__ float g_modup[768*128];             // [k][2b],[2b+1] duplicated model_out
__device__ float g_cluet[Bsz*768*32];          // normalized clues, [b][d][c] c<25
__device__ float g_sims[(size_t)Bsz*VOC];
__device__ unsigned g_hist[Bsz*65536];
__device__ int      g_thr[Bsz];
__device__ unsigned g_cnt[Bsz];
__device__ u64t     g_cand[Bsz*4096];
__device__ int   g_topidx[Bsz*KTOP];
__device__ float g_tot[Bsz*KTOP];
__device__ int   g_flags[Bsz*KTOP];
__device__ int   g_search[Bsz];
__device__ float g_part[884736];

__device__ __forceinline__ unsigned f2u(float f){
    unsigned u = __float_as_uint(f);
    return (u & 0x80000000u) ? ~u : (u | 0x80000000u);
}
__device__ __forceinline__ u64t ffma2(u64t a, u64t b, u64t c){
    u64t d;
    asm("fma.rn.f32x2 %0, %1, %2, %3;" : "=l"(d) : "l"(a), "l"(b), "l"(c));
    return d;
}

// ---------- stage 1: pooled concat x = [pool(neg)|assas|pool(neut)|pool(pos)]
__global__ void pool_concat_k(const float* __restrict__ pos, const float* __restrict__ neg,
                              const float* __restrict__ neut, const float* __restrict__ assas){
    int b=blockIdx.y, g=blockIdx.x, t=threadIdx.x;
    __shared__ float red[256];
    const float* src; int n, xoff;
    if(g==0){src=neg +(size_t)b*8*Dd; n=8; xoff=0;}
    else if(g==1){src=assas+(size_t)b*Dd; n=1; xoff=Dd;}
    else if(g==2){src=neut+(size_t)b*7*Dd; n=7; xoff=2*Dd;}
    else {src=pos +(size_t)b*9*Dd; n=9; xoff=3*Dd;}
    float m[3];
#pragma unroll
    for(int i=0;i<3;i++){int d=t+i*256; float s=0.f;
        for(int j=0;j<n;j++) s+=src[(size_t)j*Dd+d]; m[i]=s/(float)n;}
    if(g==1){
#pragma unroll
        for(int i=0;i<3;i++) g_x[b*3072+xoff+t+i*256]=m[i];
        return;
    }
    red[t]=m[0]*m[0]+m[1]*m[1]+m[2]*m[2]; __syncthreads();
    for(int s=128;s>0;s>>=1){ if(t<s) red[t]+=red[t+s]; __syncthreads(); }
    float inv=1.f/fmaxf(sqrtf(red[0]),1e-12f);
#pragma unroll
    for(int i=0;i<3;i++) g_x[b*3072+xoff+t+i*256]=m[i]*inv;
}

// ---------- stage 1b: normalized clue table transposed
__global__ void clue_norm_k(const float* __restrict__ pos, const float* __restrict__ neg,
                            const float* __restrict__ neut, const float* __restrict__ assas){
    int c=blockIdx.x, b=blockIdx.y, t=threadIdx.x;
    const float* src;
    if(c<9)       src=pos +((size_t)b*9+c)*Dd;
    else if(c<17) src=neg +((size_t)b*8+(c-9))*Dd;
    else if(c<24) src=neut+((size_t)b*7+(c-17))*Dd;
    else          src=assas+(size_t)b*Dd;
    __shared__ float red[256];
    float m[3]; float loc=0.f;
#pragma unroll
    for(int i=0;i<3;i++){ m[i]=src[t+i*256]; loc+=m[i]*m[i]; }
    red[t]=loc; __syncthreads();
    for(int s=128;s>0;s>>=1){ if(t<s) red[t]+=red[t+s]; __syncthreads(); }
    float inv=1.f/fmaxf(sqrtf(red[0]),1e-12f);
#pragma unroll
    for(int i=0;i<3;i++) g_cluet[((size_t)b*768+t+i*256)*32+c]=m[i]*inv;
}

// ---------- MLP GEMM: 64 rows, tile 64x32, K-split, FFMA2 ----------
__global__ void gemm64_k(const float* __restrict__ X, const float* __restrict__ W,
                         float* __restrict__ part, int Kdim, int Ndim, int kchunk){
    __shared__ float xs[32][64];
    __shared__ float wsd[32][64];   // duplicated cols
    int tid=threadIdx.x;            // 128
    int n0=blockIdx.x*32;
    int kbeg=blockIdx.y*kchunk, kend=min(Kdim,kbeg+kchunk);
    int rg=tid&15, cg=tid>>4;
    u64t acc2[2][4];
#pragma unroll
    for(int i=0;i<2;i++)
#pragma unroll
        for(int j=0;j<4;j++) acc2[i][j]=0ull;
    for(int k0=kbeg;k0<kend;k0+=32){
#pragma unroll
        for(int i=0;i<4;i++){
            int q=tid+i*128, r=q>>3, c4=(q&7)*4, k=k0+c4;
            float4 v=make_float4(0,0,0,0);
            if(k<kend) v=*(const float4*)(X+(size_t)r*Kdim+k);
            xs[c4+0][r]=v.x; xs[c4+1][r]=v.y; xs[c4+2][r]=v.z; xs[c4+3][r]=v.w;
        }
#pragma unroll
        for(int i=0;i<2;i++){
            int q=tid+i*128, r=q>>3, c4=(q&7)*4, k=k0+r, n=n0+c4;
            float4 v=make_float4(0,0,0,0);
            if(k<kend && n<Ndim) v=*(const float4*)(W+(size_t)k*Ndim+n);
            float4 d0=make_float4(v.x,v.x,v.y,v.y);
            float4 d1=make_float4(v.z,v.z,v.w,v.w);
            *(float4*)&wsd[r][2*c4]  =d0;
            *(float4*)&wsd[r][2*c4+4]=d1;
        }
        __syncthreads();
#pragma unroll
        for(int kk=0;kk<32;kk++){
            const u64t* ap=(const u64t*)&xs[kk][rg*4];
            const u64t* bp=(const u64t*)&wsd[kk][cg*8];
            u64t a0=ap[0], a1=ap[1];
#pragma unroll
            for(int j=0;j<4;j++){
                u64t bv=bp[j];
                acc2[0][j]=ffma2(a0,bv,acc2[0][j]);
                acc2[1][j]=ffma2(a1,bv,acc2[1][j]);
            }
        }
        __syncthreads();
    }
    float* dst=part+(size_t)blockIdx.y*Bsz*Ndim;
#pragma unroll
    for(int i=0;i<2;i++)
#pragma unroll
        for(int j=0;j<4;j++){
            int col=n0+cg*4+j;
            if(col<Ndim){
                float lo=__uint_as_float((unsigned)acc2[i][j]);
                float hi=__uint_as_float((unsigned)(acc2[i][j]>>32));
                dst[(size_t)(rg*4+2*i+0)*Ndim+col]=lo;
                dst[(size_t)(rg*4+2*i+1)*Ndim+col]=hi;
            }
        }
}

__global__ void combine_act_k(const float* __restrict__ part, const float* __restrict__ bias,
                              float* __restrict__ Y, int Ndim, int S, int act){
    int idx=blockIdx.x*blockDim.x+threadIdx.x;
    int total=Bsz*Ndim;
    if(idx>=total) return;
    int c=idx%Ndim;
    float s=bias[c];
    for(int sp=0;sp<S;sp++) s+=part[(size_t)sp*total+idx];
    Y[idx]=act?tanhf(s):s;
}

__global__ void norm_mo_k(float* __restrict__ out){
    int b=blockIdx.x, t=threadIdx.x;
    __shared__ float red[256];
    float m[3]; float loc=0.f;
#pragma unroll
    for(int i=0;i<3;i++){ m[i]=g_h4[b*768+t+i*256]; loc+=m[i]*m[i]; }
    red[t]=loc; __syncthreads();
    for(int s=128;s>0;s>>=1){ if(t<s) red[t]+=red[t+s]; __syncthreads(); }
    float inv=1.f/fmaxf(sqrtf(red[0]),1e-12f);
#pragma unroll
    for(int i=0;i<3;i++){
        float v=m[i]*inv;
        int k=t+i*256;
        g_mo[b*768+k]=v;
        out[b*768+k]=v;
        g_modup[k*128+2*b]  =v;
        g_modup[k*128+2*b+1]=v;
    }
}

// ---------- sims: tile 128 vocab x 64 batch, 128 threads, 8x8/thread, FFMA2 ----------
__global__ void __launch_bounds__(128) sims_k(const float* __restrict__ vocab){
    __shared__ float vs[16][128];
    __shared__ float msd[16][128];
    __shared__ float rinv[128];
    int tid=threadIdx.x;            // 128
    int v0=blockIdx.x*128;
    int rg=tid&15, cg=tid>>4;       // 16 row-groups x 8 col-groups
    u64t acc2[4][8];
#pragma unroll
    for(int i=0;i<4;i++)
#pragma unroll
        for(int j=0;j<8;j++) acc2[i][j]=0ull;
    float sq[4]={0,0,0,0};
    for(int k0=0;k0<768;k0+=16){
#pragma unroll
        for(int i=0;i<4;i++){
            int q=tid+i*128, r=q>>2, c4=(q&3)*4, gr=v0+r;
            float4 v=make_float4(0,0,0,0);
            if(gr<VOC) v=*(const float4*)(vocab+(size_t)gr*768+k0+c4);
            vs[c4+0][r]=v.x; vs[c4+1][r]=v.y; vs[c4+2][r]=v.z; vs[c4+3][r]=v.w;
            sq[i]+=v.x*v.x+v.y*v.y+v.z*v.z+v.w*v.w;
        }
#pragma unroll
        for(int i=0;i<4;i++){
            int q=tid+i*128;
            *(float4*)((float*)msd+q*4)=*(const float4*)(g_modup+(size_t)k0*128+q*4);
        }
        __syncthreads();
#pragma unroll
        for(int kk=0;kk<16;kk++){
            const u64t* ap=(const u64t*)&vs[kk][rg*8];
            const u64t* bp=(const u64t*)&msd[kk][cg*16];
            u64t a0=ap[0],a1=ap[1],a2=ap[2],a3=ap[3];
#pragma unroll
            for(int j=0;j<8;j++){
                u64t bv=bp[j];
                acc2[0][j]=ffma2(a0,bv,acc2[0][j]);
                acc2[1][j]=ffma2(a1,bv,acc2[1][j]);
                acc2[2][j]=ffma2(a2,bv,acc2[2][j]);
                acc2[3][j]=ffma2(a3,bv,acc2[3][j]);
            }
        }
        __syncthreads();
    }
    // reduce row sumsq among the 4 lanes sharing each row (lanes differ in tid&3)
#pragma unroll
    for(int i=0;i<4;i++){
        sq[i]+=__shfl_xor_sync(0xffffffff,sq[i],1);
        sq[i]+=__shfl_xor_sync(0xffffffff,sq[i],2);
    }
    if((tid&3)==0){
#pragma unroll
        for(int i=0;i<4;i++) rinv[(tid>>2)+32*i]=1.f/fmaxf(sqrtf(sq[i]),1e-12f);
    }
    __syncthreads();
#pragma unroll
    for(int j=0;j<8;j++){
        int col=cg*8+j;
#pragma unroll
        for(int i=0;i<4;i++){
            int rl=rg*8+2*i;
            float lo=__uint_as_float((unsigned)acc2[i][j]);
            float hi=__uint_as_float((unsigned)(acc2[i][j]>>32));
            int r0=v0+rl, r1=r0+1;
            if(r0<VOC) g_sims[(size_t)col*VOC+r0]=lo*rinv[rl];
            if(r1<VOC) g_sims[(size_t)col*VOC+r1]=hi*rinv[rl+1];
        }
    }
}

// ---------- top-512: 16-bit hist -> threshold -> collect -> exact rank select ----------
__global__ void zero_hist_k(){
    int idx=blockIdx.x*blockDim.x+threadIdx.x;
    if(idx<Bsz*65536) g_hist[idx]=0u;
    if(idx<Bsz) g_cnt[idx]=0u;
}
__global__ void hist_k(){
    int b=blockIdx.y, t=threadIdx.x;
    int start=blockIdx.x*12500, end=start+12500;
    const float* srow=g_sims+(size_t)b*VOC;
    unsigned* h=g_hist+(size_t)b*65536;
    for(int v=start+t;v<end;v+=512){
        unsigned u=f2u(srow[v]);
        atomicAdd(&h[u>>16],1u);
    }
}
__global__ void sel_k(){
    int b=blockIdx.x, t=threadIdx.x;  // 1024
    __shared__ unsigned ssum[1024];
    const unsigned* h=g_hist+(size_t)b*65536;
    int base=t*64;
    unsigned s=0;
    for(int i=0;i<64;i++) s+=h[base+i];
    ssum[t]=s; __syncthreads();
    unsigned above=0;
    for(int j=t+1;j<1024;j++) above+=ssum[j];
    if(above<512u && above+s>=512u){
        unsigned run=above;
        for(int i=63;i>=0;i--){
            unsigned hv=h[base+i];
            if(run+hv>=512u){ g_thr[b]=base+i; break; }
            run+=hv;
        }
    }
}
__global__ void collect_k(){
    int b=blockIdx.y, t=threadIdx.x;
    int start=blockIdx.x*12500, end=start+12500;
    unsigned binb=(unsigned)g_thr[b];
    const float* srow=g_sims+(size_t)b*VOC;
    for(int v=start+t;v<end;v+=512){
        unsigned u=f2u(srow[v]);
        if((u>>16)>=binb){
            unsigned pos=atomicAdd(&g_cnt[b],1u);
            if(pos<4096u) g_cand[(size_t)b*4096+pos]=((u64t)(~u)<<32)|(unsigned)v;
        }
    }
}
__global__ void final_sel_k(){
    int b=blockIdx.x, t=threadIdx.x;  // 512
    __shared__ u64t cand[4096];
    __shared__ u64t outk[512];
    int m=min(g_cnt[b],4096u);
    for(int i=t;i<m;i+=512) cand[i]=g_cand[(size_t)b*4096+i];
    __syncthreads();
    for(int i=t;i<m;i+=512){
        u64t key=cand[i]; int rank=0;
        for(int j=0;j<m;j++) rank+=(cand[j]<key);
        if(rank<512) outk[rank]=key;
    }
    __syncthreads();
    g_topidx[b*512+t]=(int)(outk[t]&0xffffffffu);
}

// ---------- gathered clue GEMM + primary/secondary (scale-invariant) ----------
__global__ void combined_k(const float* __restrict__ vocab){
    __shared__ float ws[32][64];
    __shared__ float cs[32][32];
    __shared__ int sidx[64];
    __shared__ float outc[64][32];
    int b=blockIdx.y, w0=blockIdx.x*64, tid=threadIdx.x; // 256
    if(tid<64) sidx[tid]=g_topidx[b*512+w0+tid];
    __syncthreads();
    int c=tid&31, w8=tid>>5;
    float acc[8];
#pragma unroll
    for(int i=0;i<8;i++) acc[i]=0.f;
    for(int k0=0;k0<768;k0+=32){
#pragma unroll
        for(int i=0;i<2;i++){
            int q=tid+i*256, r=q>>3, c4=(q&7)*4;
            float4 v=*(const float4*)(vocab+(size_t)sidx[r]*768+k0+c4);
            ws[c4+0][r]=v.x; ws[c4+1][r]=v.y; ws[c4+2][r]=v.z; ws[c4+3][r]=v.w;
        }
#pragma unroll
        for(int i=0;i<4;i++){
            int q=tid+i*256, kk=q>>5, cc=q&31;
            cs[kk][cc]=(cc<25)?g_cluet[((size_t)b*768+k0+kk)*32+cc]:0.f;
        }
        __syncthreads();
#pragma unroll
        for(int kk=0;kk<32;kk++){
            float cv=cs[kk][c];
            float4 a0=*(const float4*)&ws[kk][w8*8];
            float4 a1=*(const float4*)&ws[kk][w8*8+4];
            acc[0]+=a0.x*cv; acc[1]+=a0.y*cv; acc[2]+=a0.z*cv; acc[3]+=a0.w*cv;
            acc[4]+=a1.x*cv; acc[5]+=a1.y*cv; acc[6]+=a1.z*cv; acc[7]+=a1.w*cv;
        }
        __syncthreads();
    }
#pragma unroll
    for(int i=0;i<8;i++) outc[w8*8+i][c]=acc[i];
    __syncthreads();
    if(tid<64){
        float* row=outc[tid];
        float mbest=-1e30f; int jbest=9;
        for(int j=9;j<25;j++){ float v=row[j]; if(v>mbest){mbest=v; jbest=j;} }
        int primary=0;
        for(int p=0;p<9;p++) primary+=(row[p]>=mbest);
        float sec=(jbest<17)?0.f:((jbest<24)?1.f:-10.f);
        g_tot[b*512+w0+tid]=(float)primary+sec;
    }
}

// ---------- rank with exact top_k tie semantics ----------
__global__ void rank_k(){
    int b=blockIdx.x, t=threadIdx.x; // 512
    __shared__ float tv[512];
    tv[t]=g_tot[b*512+t]; __syncthreads();
    float mv=tv[t]; int gt=0, lt=0, eqb=0;
    for(int j=0;j<512;j++){
        float o=tv[j];
        gt+=(o>mv); lt+=(o<mv); eqb+=((o==mv)&&(j<t));
    }
    int rmax=gt+eqb, rmin=lt+eqb;
    g_flags[b*512+t]=((rmax<256)?1:0)|((rmin<256)?2:0);
    if(rmax==0) g_search[b]=g_topidx[b*512+t];
}

// ---------- final pooled outputs ----------
__global__ void final_k(const float* __restrict__ vocab, float* __restrict__ out){
    int b=blockIdx.x, t=threadIdx.x; // 256
    __shared__ float red[256];
    float amax[3]={0,0,0}, amin[3]={0,0,0};
    const int* ti=g_topidx+b*512;
    const int* fl=g_flags+b*512;
    for(int w=0;w<512;w++){
        int f=fl[w];
        if(f){
            const float* row=vocab+(size_t)ti[w]*768;
#pragma unroll
            for(int i=0;i<3;i++){
                float v=row[t+i*256];
                if(f&1) amax[i]+=v;
                if(f&2) amin[i]+=v;
            }
        }
    }
    float loc=0.f;
#pragma unroll
    for(int i=0;i<3;i++){ amax[i]*=(1.f/256.f); loc+=amax[i]*amax[i]; }
    red[t]=loc; __syncthreads();
    for(int s=128;s>0;s>>=1){ if(t<s) red[t]+=red[t+s]; __syncthreads(); }
    float inv=1.f/fmaxf(sqrtf(red[0]),1e-12f);
#pragma unroll
    for(int i=0;i<3;i++) out[2*49152+b*768+t+i*256]=amax[i]*inv;
    __syncthreads();
    loc=0.f;
#pragma unroll
    for(int i=0;i<3;i++){ amin[i]*=(1.f/256.f); loc+=amin[i]*amin[i]; }
    red[t]=loc; __syncthreads();
    for(int s=128;s>0;s>>=1){ if(t<s) red[t]+=red[t+s]; __syncthreads(); }
    inv=1.f/fmaxf(sqrtf(red[0]),1e-12f);
#pragma unroll
    for(int i=0;i<3;i++) out[3*49152+b*768+t+i*256]=amin[i]*inv;
    int sw=g_search[b];
#pragma unroll
    for(int i=0;i<3;i++) out[49152+b*768+t+i*256]=vocab[(size_t)sw*768+t+i*256];
}

extern "C" void kernel_launch(void* const* d_in, const int* in_sizes, int n_in,
                              void* d_out, int out_size){
    const float* pos  =(const float*)d_in[0];
    const float* neg  =(const float*)d_in[1];
    const float* neut =(const float*)d_in[2];
    const float* assas=(const float*)d_in[3];
    const float* vocab=(const float*)d_in[4];
    const float* W1=(const float*)d_in[5];  const float* b1=(const float*)d_in[6];
    const float* W2=(const float*)d_in[7];  const float* b2=(const float*)d_in[8];
    const float* W3=(const float*)d_in[9];  const float* b3=(const float*)d_in[10];
    const float* W4=(const float*)d_in[11]; const float* b4=(const float*)d_in[12];
    float* out=(float*)d_out;

    float *gx, *gh1, *gh2, *gh3, *gh4, *gpart;
    cudaGetSymbolAddress((void**)&gx,   g_x);
    cudaGetSymbolAddress((void**)&gh1,  g_h1);
    cudaGetSymbolAddress((void**)&gh2,  g_h2);
    cudaGetSymbolAddress((void**)&gh3,  g_h3);
    cudaGetSymbolAddress((void**)&gh4,  g_h4);
    cudaGetSymbolAddress((void**)&gpart,g_part);

    zero_hist_k<<<(Bsz*65536+1023)/1024,1024>>>();
    pool_concat_k<<<dim3(4,64),256>>>(pos,neg,neut,assas);
    clue_norm_k<<<dim3(25,64),256>>>(pos,neg,neut,assas);

    // L1: 3072->2304, 4 splits
    gemm64_k<<<dim3(72,4),128>>>(gx,W1,gpart,3072,2304,768);
    combine_act_k<<<(64*2304+255)/256,256>>>(gpart,b1,gh1,2304,4,1);
    // L2: 2304->1700, 6 splits
    gemm64_k<<<dim3(54,6),128>>>(gh1,W2,gpart,2304,1700,384);
    combine_act_k<<<(64*1700+255)/256,256>>>(gpart,b2,gh2,1700,6,1);
    // L3: 1700->1000, 9 splits
    gemm64_k<<<dim3(32,9),128>>>(gh2,W3,gpart,1700,1000,192);
    combine_act_k<<<(64*1000+255)/256,256>>>(gpart,b3,gh3,1000,9,1);
    // L4: 1000->768, 11 splits (no tanh)
    gemm64_k<<<dim3(24,11),128>>>(gh3,W4,gpart,1000,768,96);
    combine_act_k<<<(64*768+255)/256,256>>>(gpart,b4,gh4,768,11,0);

    norm_mo_k<<<64,256>>>(out);
    sims_k<<<(VOC+127)/128,128>>>(vocab);

    hist_k<<<dim3(8,64),512>>>();
    sel_k<<<64,1024>>>();
    collect_k<<<dim3(8,64),512>>>();
    final_sel_k<<<64,512>>>();

    combined_k<<<dim3(8,64),256>>>(vocab);
    rank_k<<<64,512>>>();
    final_k<<<64,256>>>(vocab,out);
}

// round 4
// speedup vs baseline: 1.4029x; 1.2770x over previous
#include <cuda_runtime.h>
#include <math.h>
#include <stdint.h>

#define Bsz 64
#define Dd  768
#define VOC 100000
#define KTOP 512

typedef unsigned long long u64t;

// ---------- scratch ----------
__device__ float g_x [Bsz*3072];
__device__ float g_h1[Bsz*2304];
__device__ float g_h2[Bsz*1700];
__device__ float g_h3[Bsz*1000];
__device__ float g_h4[Bsz*768];
__device__ float g_mo[Bsz*768];
__device__ float g_modup[768*128];
__device__ float g_cluet[Bsz*768*32];
__device__ float g_sims[(size_t)Bsz*VOC];
__device__ unsigned g_hist[Bsz*65536];
__device__ int      g_thr[Bsz];
__device__ unsigned g_cnt[Bsz];
__device__ u64t     g_cand[Bsz*4096];
__device__ int   g_topidx[Bsz*KTOP];
__device__ float g_tot[Bsz*KTOP];
__device__ int   g_flags[Bsz*KTOP];
__device__ int   g_search[Bsz];
__device__ float g_part[2359296];
__device__ float g_pp[Bsz*8*2*768];

__device__ __forceinline__ unsigned f2u(float f){
    unsigned u = __float_as_uint(f);
    return (u & 0x80000000u) ? ~u : (u | 0x80000000u);
}
__device__ __forceinline__ u64t ffma2(u64t a, u64t b, u64t c){
    u64t d;
    asm("fma.rn.f32x2 %0, %1, %2, %3;" : "=l"(d) : "l"(a), "l"(b), "l"(c));
    return d;
}
__device__ __forceinline__ float u2lo(u64t v){ return __uint_as_float((unsigned)v); }
__device__ __forceinline__ float u2hi(u64t v){ return __uint_as_float((unsigned)(v>>32)); }

// ---------- stage 1 ----------
__global__ void pool_concat_k(const float* __restrict__ pos, const float* __restrict__ neg,
                              const float* __restrict__ neut, const float* __restrict__ assas){
    int b=blockIdx.y, g=blockIdx.x, t=threadIdx.x;
    __shared__ float red[256];
    const float* src; int n, xoff;
    if(g==0){src=neg +(size_t)b*8*Dd; n=8; xoff=0;}
    else if(g==1){src=assas+(size_t)b*Dd; n=1; xoff=Dd;}
    else if(g==2){src=neut+(size_t)b*7*Dd; n=7; xoff=2*Dd;}
    else {src=pos +(size_t)b*9*Dd; n=9; xoff=3*Dd;}
    float m[3];
#pragma unroll
    for(int i=0;i<3;i++){int d=t+i*256; float s=0.f;
        for(int j=0;j<n;j++) s+=src[(size_t)j*Dd+d]; m[i]=s/(float)n;}
    if(g==1){
#pragma unroll
        for(int i=0;i<3;i++) g_x[b*3072+xoff+t+i*256]=m[i];
        return;
    }
    red[t]=m[0]*m[0]+m[1]*m[1]+m[2]*m[2]; __syncthreads();
    for(int s=128;s>0;s>>=1){ if(t<s) red[t]+=red[t+s]; __syncthreads(); }
    float inv=1.f/fmaxf(sqrtf(red[0]),1e-12f);
#pragma unroll
    for(int i=0;i<3;i++) g_x[b*3072+xoff+t+i*256]=m[i]*inv;
}

__global__ void clue_norm_k(const float* __restrict__ pos, const float* __restrict__ neg,
                            const float* __restrict__ neut, const float* __restrict__ assas){
    int c=blockIdx.x, b=blockIdx.y, t=threadIdx.x;
    const float* src;
    if(c<9)       src=pos +((size_t)b*9+c)*Dd;
    else if(c<17) src=neg +((size_t)b*8+(c-9))*Dd;
    else if(c<24) src=neut+((size_t)b*7+(c-17))*Dd;
    else          src=assas+(size_t)b*Dd;
    __shared__ float red[256];
    float m[3]; float loc=0.f;
#pragma unroll
    for(int i=0;i<3;i++){ m[i]=src[t+i*256]; loc+=m[i]*m[i]; }
    red[t]=loc; __syncthreads();
    for(int s=128;s>0;s>>=1){ if(t<s) red[t]+=red[t+s]; __syncthreads(); }
    float inv=1.f/fmaxf(sqrtf(red[0]),1e-12f);
#pragma unroll
    for(int i=0;i<3;i++) g_cluet[((size_t)b*768+t+i*256)*32+c]=m[i]*inv;
}

// ---------- MLP GEMM transposed mapping: block = 64 neurons x 64 batch rows ----------
// part[split][row][n] += sum_k X[row][k]*W[k][n]; W streamed contiguously; X dup-transposed in smem
__global__ void __launch_bounds__(128) gemmT_k(const float* __restrict__ X, const float* __restrict__ W,
        float* __restrict__ part, int Kdim, int Ndim, int kchunk){
    __shared__ float ws[16][68];     // [kk][n]
    __shared__ float msd[16][130];   // [kk][2*row] duplicated X
    int tid=threadIdx.x;
    int n0=blockIdx.x*64;
    int kbeg=blockIdx.y*kchunk, kend=min(Kdim,kbeg+kchunk);
    int rg=tid&15, cg=tid>>4;
    u64t acc2[2][8];
#pragma unroll
    for(int i=0;i<2;i++)
#pragma unroll
        for(int j=0;j<8;j++) acc2[i][j]=0ull;

    float4 wr[2], xr[2];
    // prefetch first tile
#pragma unroll
    for(int i=0;i<2;i++){
        int q=tid+i*128; int kr=q>>4, c4=(q&15)*4;
        int k=kbeg+kr, n=n0+c4;
        float4 v=make_float4(0,0,0,0);
        if(k<kend && n<Ndim) v=*(const float4*)(W+(size_t)k*Ndim+n);
        wr[i]=v;
    }
#pragma unroll
    for(int i=0;i<2;i++){
        int q=tid+i*128; int r=q>>2, c4=(q&3)*4;
        int k=kbeg+c4;
        float4 v=make_float4(0,0,0,0);
        if(k<kend) v=*(const float4*)(X+(size_t)r*Kdim+k);
        xr[i]=v;
    }
    for(int k0=kbeg;k0<kend;k0+=16){
#pragma unroll
        for(int i=0;i<2;i++){
            int q=tid+i*128; int kr=q>>4, c4=(q&15)*4;
            *(float4*)&ws[kr][c4]=wr[i];
        }
#pragma unroll
        for(int i=0;i<2;i++){
            int q=tid+i*128; int r=q>>2, c4=(q&3)*4;
            float vv[4]={xr[i].x,xr[i].y,xr[i].z,xr[i].w};
#pragma unroll
            for(int j=0;j<4;j++){
                float2 d=make_float2(vv[j],vv[j]);
                *(float2*)&msd[c4+j][2*r]=d;
            }
        }
        __syncthreads();
        int kn=k0+16;
        if(kn<kend){
#pragma unroll
            for(int i=0;i<2;i++){
                int q=tid+i*128; int kr=q>>4, c4=(q&15)*4;
                int k=kn+kr, n=n0+c4;
                float4 v=make_float4(0,0,0,0);
                if(k<kend && n<Ndim) v=*(const float4*)(W+(size_t)k*Ndim+n);
                wr[i]=v;
            }
#pragma unroll
            for(int i=0;i<2;i++){
                int q=tid+i*128; int r=q>>2, c4=(q&3)*4;
                int k=kn+c4;
                float4 v=make_float4(0,0,0,0);
                if(k<kend) v=*(const float4*)(X+(size_t)r*Kdim+k);
                xr[i]=v;
            }
        }
#pragma unroll
        for(int kk=0;kk<16;kk++){
            const u64t* ap=(const u64t*)&ws[kk][rg*4];
            u64t a0=ap[0], a1=ap[1];
            const u64t* bp=(const u64t*)&msd[kk][cg*16];
#pragma unroll
            for(int j=0;j<8;j++){
                u64t bv=bp[j];
                acc2[0][j]=ffma2(a0,bv,acc2[0][j]);
                acc2[1][j]=ffma2(a1,bv,acc2[1][j]);
            }
        }
        __syncthreads();
    }
    float* dst=part+(size_t)blockIdx.y*Bsz*Ndim;
#pragma unroll
    for(int i=0;i<2;i++){
        int n=n0+rg*4+2*i;
#pragma unroll
        for(int j=0;j<8;j++){
            int row=cg*8+j;
            if(n<Ndim)   dst[(size_t)row*Ndim+n]  =u2lo(acc2[i][j]);
            if(n+1<Ndim) dst[(size_t)row*Ndim+n+1]=u2hi(acc2[i][j]);
        }
    }
}

__global__ void combine_act_k(const float* __restrict__ part, const float* __restrict__ bias,
                              float* __restrict__ Y, int Ndim, int S, int act){
    int idx=blockIdx.x*blockDim.x+threadIdx.x;
    int total=Bsz*Ndim;
    if(idx>=total) return;
    int c=idx%Ndim;
    float s=bias[c];
    for(int sp=0;sp<S;sp++) s+=part[(size_t)sp*total+idx];
    Y[idx]=act?tanhf(s):s;
}

__global__ void norm_mo_k(float* __restrict__ out){
    int b=blockIdx.x, t=threadIdx.x;
    __shared__ float red[256];
    float m[3]; float loc=0.f;
#pragma unroll
    for(int i=0;i<3;i++){ m[i]=g_h4[b*768+t+i*256]; loc+=m[i]*m[i]; }
    red[t]=loc; __syncthreads();
    for(int s=128;s>0;s>>=1){ if(t<s) red[t]+=red[t+s]; __syncthreads(); }
    float inv=1.f/fmaxf(sqrtf(red[0]),1e-12f);
#pragma unroll
    for(int i=0;i<3;i++){
        float v=m[i]*inv;
        int k=t+i*256;
        g_mo[b*768+k]=v;
        out[b*768+k]=v;
        g_modup[k*128+2*b]  =v;
        g_modup[k*128+2*b+1]=v;
    }
}

// ---------- sims: 128 vocab x 64 batch, FFMA2, reg-prefetch pipeline ----------
__global__ void __launch_bounds__(128) sims_k(const float* __restrict__ vocab){
    __shared__ float vs[16][128];
    __shared__ float msd[16][128];
    __shared__ float rinv[128];
    int tid=threadIdx.x;
    int v0=blockIdx.x*128;
    int rg=tid&15, cg=tid>>4;
    u64t acc2[4][8];
#pragma unroll
    for(int i=0;i<4;i++)
#pragma unroll
        for(int j=0;j<8;j++) acc2[i][j]=0ull;
    float sq[4]={0,0,0,0};
    float4 va[4], vb[4];
#pragma unroll
    for(int i=0;i<4;i++){
        int q=tid+i*128, r=q>>2, c4=(q&3)*4, gr=v0+r;
        va[i]=make_float4(0,0,0,0);
        if(gr<VOC) va[i]=*(const float4*)(vocab+(size_t)gr*768+c4);
        vb[i]=*(const float4*)(g_modup+(size_t)q*4);
    }
    for(int k0=0;k0<768;k0+=16){
#pragma unroll
        for(int i=0;i<4;i++){
            int q=tid+i*128, r=q>>2, c4=(q&3)*4;
            float4 v=va[i];
            vs[c4+0][r]=v.x; vs[c4+1][r]=v.y; vs[c4+2][r]=v.z; vs[c4+3][r]=v.w;
            sq[i]+=v.x*v.x+v.y*v.y+v.z*v.z+v.w*v.w;
            *(float4*)((float*)msd+q*4)=vb[i];
        }
        __syncthreads();
        int kn=k0+16;
        if(kn<768){
#pragma unroll
            for(int i=0;i<4;i++){
                int q=tid+i*128, r=q>>2, c4=(q&3)*4, gr=v0+r;
                va[i]=make_float4(0,0,0,0);
                if(gr<VOC) va[i]=*(const float4*)(vocab+(size_t)gr*768+kn+c4);
                vb[i]=*(const float4*)(g_modup+(size_t)kn*128+q*4);
            }
        }
#pragma unroll
        for(int kk=0;kk<16;kk++){
            const u64t* ap=(const u64t*)&vs[kk][rg*8];
            const u64t* bp=(const u64t*)&msd[kk][cg*16];
            u64t a0=ap[0],a1=ap[1],a2=ap[2],a3=ap[3];
#pragma unroll
            for(int j=0;j<8;j++){
                u64t bv=bp[j];
                acc2[0][j]=ffma2(a0,bv,acc2[0][j]);
                acc2[1][j]=ffma2(a1,bv,acc2[1][j]);
                acc2[2][j]=ffma2(a2,bv,acc2[2][j]);
                acc2[3][j]=ffma2(a3,bv,acc2[3][j]);
            }
        }
        __syncthreads();
    }
#pragma unroll
    for(int i=0;i<4;i++){
        sq[i]+=__shfl_xor_sync(0xffffffff,sq[i],1);
        sq[i]+=__shfl_xor_sync(0xffffffff,sq[i],2);
    }
    if((tid&3)==0){
#pragma unroll
        for(int i=0;i<4;i++) rinv[(tid>>2)+32*i]=1.f/fmaxf(sqrtf(sq[i]),1e-12f);
    }
    __syncthreads();
#pragma unroll
    for(int j=0;j<8;j++){
        int col=cg*8+j;
#pragma unroll
        for(int i=0;i<4;i++){
            int rl=rg*8+2*i;
            int r0=v0+rl, r1=r0+1;
            if(r0<VOC) g_sims[(size_t)col*VOC+r0]=u2lo(acc2[i][j])*rinv[rl];
            if(r1<VOC) g_sims[(size_t)col*VOC+r1]=u2hi(acc2[i][j])*rinv[rl+1];
        }
    }
}

// ---------- top-512 ----------
__global__ void zero_hist_k(){
    int idx=blockIdx.x*blockDim.x+threadIdx.x;
    if(idx<Bsz*65536) g_hist[idx]=0u;
    if(idx<Bsz) g_cnt[idx]=0u;
}
__global__ void hist_k(){
    int b=blockIdx.y, t=threadIdx.x;
    int start=blockIdx.x*12500, end=start+12500;
    const float* srow=g_sims+(size_t)b*VOC;
    unsigned* h=g_hist+(size_t)b*65536;
    for(int v=start+t;v<end;v+=512){
        unsigned u=f2u(srow[v]);
        atomicAdd(&h[u>>16],1u);
    }
}
__global__ void sel_k(){
    int b=blockIdx.x, t=threadIdx.x;  // 1024
    __shared__ unsigned ssum[1024];
    const unsigned* h=g_hist+(size_t)b*65536;
    int base=t*64;
    unsigned s=0;
    for(int i=0;i<64;i++) s+=h[base+i];
    ssum[t]=s; __syncthreads();
    unsigned above=0;
    for(int j=t+1;j<1024;j++) above+=ssum[j];
    if(above<512u && above+s>=512u){
        unsigned run=above;
        for(int i=63;i>=0;i--){
            unsigned hv=h[base+i];
            if(run+hv>=512u){ g_thr[b]=base+i; break; }
            run+=hv;
        }
    }
}
__global__ void collect_k(){
    int b=blockIdx.y, t=threadIdx.x;
    int start=blockIdx.x*12500, end=start+12500;
    unsigned binb=(unsigned)g_thr[b];
    const float* srow=g_sims+(size_t)b*VOC;
    for(int v=start+t;v<end;v+=512){
        unsigned u=f2u(srow[v]);
        if((u>>16)>=binb){
            unsigned pos=atomicAdd(&g_cnt[b],1u);
            if(pos<4096u) g_cand[(size_t)b*4096+pos]=((u64t)(~u)<<32)|(unsigned)v;
        }
    }
}
__global__ void final_sel_k(){
    int b=blockIdx.x, t=threadIdx.x;  // 512
    __shared__ u64t cand[4096];
    __shared__ u64t outk[512];
    int m=min(g_cnt[b],4096u);
    for(int i=t;i<m;i+=512) cand[i]=g_cand[(size_t)b*4096+i];
    __syncthreads();
    for(int i=t;i<m;i+=512){
        u64t key=cand[i]; int rank=0;
        for(int j=0;j<m;j++) rank+=(cand[j]<key);
        if(rank<512) outk[rank]=key;
    }
    __syncthreads();
    g_topidx[b*512+t]=(int)(outk[t]&0xffffffffu);
}

// ---------- gathered clue GEMM + primary/secondary ----------
__global__ void combined_k(const float* __restrict__ vocab){
    __shared__ float ws[32][64];
    __shared__ float cs[32][32];
    __shared__ int sidx[64];
    __shared__ float outc[64][32];
    int b=blockIdx.y, w0=blockIdx.x*64, tid=threadIdx.x; // 256
    if(tid<64) sidx[tid]=g_topidx[b*512+w0+tid];
    __syncthreads();
    int c=tid&31, w8=tid>>5;
    float acc[8];
#pragma unroll
    for(int i=0;i<8;i++) acc[i]=0.f;
    for(int k0=0;k0<768;k0+=32){
#pragma unroll
        for(int i=0;i<2;i++){
            int q=tid+i*256, r=q>>3, c4=(q&7)*4;
            float4 v=*(const float4*)(vocab+(size_t)sidx[r]*768+k0+c4);
            ws[c4+0][r]=v.x; ws[c4+1][r]=v.y; ws[c4+2][r]=v.z; ws[c4+3][r]=v.w;
        }
#pragma unroll
        for(int i=0;i<4;i++){
            int q=tid+i*256, kk=q>>5, cc=q&31;
            cs[kk][cc]=(cc<25)?g_cluet[((size_t)b*768+k0+kk)*32+cc]:0.f;
        }
        __syncthreads();
#pragma unroll
        for(int kk=0;kk<32;kk++){
            float cv=cs[kk][c];
            float4 a0=*(const float4*)&ws[kk][w8*8];
            float4 a1=*(const float4*)&ws[kk][w8*8+4];
            acc[0]+=a0.x*cv; acc[1]+=a0.y*cv; acc[2]+=a0.z*cv; acc[3]+=a0.w*cv;
            acc[4]+=a1.x*cv; acc[5]+=a1.y*cv; acc[6]+=a1.z*cv; acc[7]+=a1.w*cv;
        }
        __syncthreads();
    }
#pragma unroll
    for(int i=0;i<8;i++) outc[w8*8+i][c]=acc[i];
    __syncthreads();
    if(tid<64){
        float* row=outc[tid];
        float mbest=-1e30f; int jbest=9;
        for(int j=9;j<25;j++){ float v=row[j]; if(v>mbest){mbest=v; jbest=j;} }
        int primary=0;
        for(int p=0;p<9;p++) primary+=(row[p]>=mbest);
        float sec=(jbest<17)?0.f:((jbest<24)?1.f:-10.f);
        g_tot[b*512+w0+tid]=(float)primary+sec;
    }
}

// ---------- rank ----------
__global__ void rank_k(){
    int b=blockIdx.x, t=threadIdx.x; // 512
    __shared__ float tv[512];
    tv[t]=g_tot[b*512+t]; __syncthreads();
    float mv=tv[t]; int gt=0, lt=0, eqb=0;
    for(int j=0;j<512;j++){
        float o=tv[j];
        gt+=(o>mv); lt+=(o<mv); eqb+=((o==mv)&&(j<t));
    }
    int rmax=gt+eqb, rmin=lt+eqb;
    g_flags[b*512+t]=((rmax<256)?1:0)|((rmin<256)?2:0);
    if(rmax==0) g_search[b]=g_topidx[b*512+t];
}

// ---------- final pooled outputs: partial accumulate + reduce ----------
__global__ void final_acc_k(const float* __restrict__ vocab){
    int b=blockIdx.y, c=blockIdx.x, t=threadIdx.x; // 256
    const int* ti=g_topidx+b*512+c*64;
    const int* fl=g_flags+b*512+c*64;
    float amax[3]={0,0,0}, amin[3]={0,0,0};
    for(int w=0;w<64;w++){
        int f=fl[w];
        if(f){
            const float* row=vocab+(size_t)ti[w]*768;
#pragma unroll
            for(int i=0;i<3;i++){
                float v=row[t+i*256];
                if(f&1) amax[i]+=v;
                if(f&2) amin[i]+=v;
            }
        }
    }
    float* pp=g_pp+(size_t)(b*8+c)*2*768;
#pragma unroll
    for(int i=0;i<3;i++){
        pp[t+i*256]=amax[i];
        pp[768+t+i*256]=amin[i];
    }
}
__global__ void final_red_k(const float* __restrict__ vocab, float* __restrict__ out){
    int b=blockIdx.x, t=threadIdx.x; // 256
    __shared__ float red[256];
    float amax[3]={0,0,0}, amin[3]={0,0,0};
    for(int c=0;c<8;c++){
        const float* pp=g_pp+(size_t)(b*8+c)*2*768;
#pragma unroll
        for(int i=0;i<3;i++){
            amax[i]+=pp[t+i*256];
            amin[i]+=pp[768+t+i*256];
        }
    }
    float loc=0.f;
#pragma unroll
    for(int i=0;i<3;i++){ amax[i]*=(1.f/256.f); loc+=amax[i]*amax[i]; }
    red[t]=loc; __syncthreads();
    for(int s=128;s>0;s>>=1){ if(t<s) red[t]+=red[t+s]; __syncthreads(); }
    float inv=1.f/fmaxf(sqrtf(red[0]),1e-12f);
#pragma unroll
    for(int i=0;i<3;i++) out[2*49152+b*768+t+i*256]=amax[i]*inv;
    __syncthreads();
    loc=0.f;
#pragma unroll
    for(int i=0;i<3;i++){ amin[i]*=(1.f/256.f); loc+=amin[i]*amin[i]; }
    red[t]=loc; __syncthreads();
    for(int s=128;s>0;s>>=1){ if(t<s) red[t]+=red[t+s]; __syncthreads(); }
    inv=1.f/fmaxf(sqrtf(red[0]),1e-12f);
#pragma unroll
    for(int i=0;i<3;i++) out[3*49152+b*768+t+i*256]=amin[i]*inv;
    int sw=g_search[b];
#pragma unroll
    for(int i=0;i<3;i++) out[49152+b*768+t+i*256]=vocab[(size_t)sw*768+t+i*256];
}

extern "C" void kernel_launch(void* const* d_in, const int* in_sizes, int n_in,
                              void* d_out, int out_size){
    const float* pos  =(const float*)d_in[0];
    const float* neg  =(const float*)d_in[1];
    const float* neut =(const float*)d_in[2];
    const float* assas=(const float*)d_in[3];
    const float* vocab=(const float*)d_in[4];
    const float* W1=(const float*)d_in[5];  const float* b1=(const float*)d_in[6];
    const float* W2=(const float*)d_in[7];  const float* b2=(const float*)d_in[8];
    const float* W3=(const float*)d_in[9];  const float* b3=(const float*)d_in[10];
    const float* W4=(const float*)d_in[11]; const float* b4=(const float*)d_in[12];
    float* out=(float*)d_out;

    float *gx, *gh1, *gh2, *gh3, *gh4, *gpart;
    cudaGetSymbolAddress((void**)&gx,   g_x);
    cudaGetSymbolAddress((void**)&gh1,  g_h1);
    cudaGetSymbolAddress((void**)&gh2,  g_h2);
    cudaGetSymbolAddress((void**)&gh3,  g_h3);
    cudaGetSymbolAddress((void**)&gh4,  g_h4);
    cudaGetSymbolAddress((void**)&gpart,g_part);

    zero_hist_k<<<(Bsz*65536+1023)/1024,1024>>>();
    pool_concat_k<<<dim3(4,64),256>>>(pos,neg,neut,assas);
    clue_norm_k<<<dim3(25,64),256>>>(pos,neg,neut,assas);

    // L1: K=3072 N=2304, 36 ntiles x 16 splits (kchunk 192)
    gemmT_k<<<dim3(36,16),128>>>(gx,W1,gpart,3072,2304,192);
    combine_act_k<<<(64*2304+255)/256,256>>>(gpart,b1,gh1,2304,16,1);
    // L2: K=2304 N=1700, 27 x 18 (kchunk 128)
    gemmT_k<<<dim3(27,18),128>>>(gh1,W2,gpart,2304,1700,128);
    combine_act_k<<<(64*1700+255)/256,256>>>(gpart,b2,gh2,1700,18,1);
    // L3: K=1700 N=1000, 16 x 27 (kchunk 64)
    gemmT_k<<<dim3(16,27),128>>>(gh2,W3,gpart,1700,1000,64);
    combine_act_k<<<(64*1000+255)/256,256>>>(gpart,b3,gh3,1000,27,1);
    // L4: K=1000 N=768, 12 x 32 (kchunk 32)
    gemmT_k<<<dim3(12,32),128>>>(gh3,W4,gpart,1000,768,32);
    combine_act_k<<<(64*768+255)/256,256>>>(gpart,b4,gh4,768,32,0);

    norm_mo_k<<<64,256>>>(out);
    sims_k<<<(VOC+127)/128,128>>>(vocab);

    hist_k<<<dim3(8,64),512>>>();
    sel_k<<<64,1024>>>();
    collect_k<<<dim3(8,64),512>>>();
    final_sel_k<<<64,512>>>();

    combined_k<<<dim3(8,64),256>>>(vocab);
    rank_k<<<64,512>>>();
    final_acc_k<<<dim3(8,64),256>>>(vocab);
    final_red_k<<<64,256>>>(vocab,out);
}

// round 5
// speedup vs baseline: 1.5701x; 1.1191x over previous
#include <cuda_runtime.h>
#include <cuda_bf16.h>
#include <math.h>
#include <stdint.h>

#define Bsz 64
#define Dd  768
#define VOC 100000
#define KTOP 512

typedef unsigned long long u64t;

// ---------- scratch ----------
__device__ float g_x [Bsz*3072];
__device__ float g_h1[Bsz*2304];
__device__ float g_h2[Bsz*1700];
__device__ float g_h3[Bsz*1000];
__device__ float g_h4[Bsz*768];
__device__ float g_mo[Bsz*768];
__device__ uint2 g_bfh[48*8*32];               // B fragments (hi) per [k16][n8][lane]
__device__ uint2 g_bfl[48*8*32];               // B fragments (lo)
__device__ float g_cluet[Bsz*768*32];
__device__ float g_sims[(size_t)Bsz*VOC];
__device__ unsigned g_hist[Bsz*65536];
__device__ int      g_thr[Bsz];
__device__ unsigned g_cnt[Bsz];
__device__ u64t     g_cand[Bsz*4096];
__device__ int   g_topidx[Bsz*KTOP];
__device__ float g_tot[Bsz*KTOP];
__device__ int   g_flags[Bsz*KTOP];
__device__ int   g_search[Bsz];
__device__ float g_part[3538944];
__device__ float g_pp[Bsz*8*2*768];

__device__ __forceinline__ unsigned f2u(float f){
    unsigned u = __float_as_uint(f);
    return (u & 0x80000000u) ? ~u : (u | 0x80000000u);
}
__device__ __forceinline__ u64t ffma2(u64t a, u64t b, u64t c){
    u64t d;
    asm("fma.rn.f32x2 %0, %1, %2, %3;" : "=l"(d) : "l"(a), "l"(b), "l"(c));
    return d;
}
__device__ __forceinline__ float u2lo(u64t v){ return __uint_as_float((unsigned)v); }
__device__ __forceinline__ float u2hi(u64t v){ return __uint_as_float((unsigned)(v>>32)); }

__device__ __forceinline__ unsigned packbf(__nv_bfloat16 a, __nv_bfloat16 b){
    __nv_bfloat162 v = __halves2bfloat162(a, b);
    return *(unsigned*)&v;
}
// split float2 into packed bf16x2 hi and lo
__device__ __forceinline__ void split2(float2 f, unsigned &hi, unsigned &lo){
    __nv_bfloat16 h0=__float2bfloat16(f.x), h1=__float2bfloat16(f.y);
    float r0=f.x-__bfloat162float(h0), r1=f.y-__bfloat162float(h1);
    hi = packbf(h0,h1);
    lo = packbf(__float2bfloat16(r0), __float2bfloat16(r1));
}

#define MMA_BF16(D,A0,A1,A2,A3,B0,B1) \
  asm volatile("mma.sync.aligned.m16n8k16.row.col.f32.bf16.bf16.f32 " \
    "{%0,%1,%2,%3},{%4,%5,%6,%7},{%8,%9},{%0,%1,%2,%3};" \
    : "+f"(D[0]),"+f"(D[1]),"+f"(D[2]),"+f"(D[3]) \
    : "r"(A0),"r"(A1),"r"(A2),"r"(A3),"r"(B0),"r"(B1))

// ---------- stage 1 ----------
__global__ void pool_concat_k(const float* __restrict__ pos, const float* __restrict__ neg,
                              const float* __restrict__ neut, const float* __restrict__ assas){
    int b=blockIdx.y, g=blockIdx.x, t=threadIdx.x;
    __shared__ float red[256];
    const float* src; int n, xoff;
    if(g==0){src=neg +(size_t)b*8*Dd; n=8; xoff=0;}
    else if(g==1){src=assas+(size_t)b*Dd; n=1; xoff=Dd;}
    else if(g==2){src=neut+(size_t)b*7*Dd; n=7; xoff=2*Dd;}
    else {src=pos +(size_t)b*9*Dd; n=9; xoff=3*Dd;}
    float m[3];
#pragma unroll
    for(int i=0;i<3;i++){int d=t+i*256; float s=0.f;
        for(int j=0;j<n;j++) s+=src[(size_t)j*Dd+d]; m[i]=s/(float)n;}
    if(g==1){
#pragma unroll
        for(int i=0;i<3;i++) g_x[b*3072+xoff+t+i*256]=m[i];
        return;
    }
    red[t]=m[0]*m[0]+m[1]*m[1]+m[2]*m[2]; __syncthreads();
    for(int s=128;s>0;s>>=1){ if(t<s) red[t]+=red[t+s]; __syncthreads(); }
    float inv=1.f/fmaxf(sqrtf(red[0]),1e-12f);
#pragma unroll
    for(int i=0;i<3;i++) g_x[b*3072+xoff+t+i*256]=m[i]*inv;
}

__global__ void clue_norm_k(const float* __restrict__ pos, const float* __restrict__ neg,
                            const float* __restrict__ neut, const float* __restrict__ assas){
    int c=blockIdx.x, b=blockIdx.y, t=threadIdx.x;
    const float* src;
    if(c<9)       src=pos +((size_t)b*9+c)*Dd;
    else if(c<17) src=neg +((size_t)b*8+(c-9))*Dd;
    else if(c<24) src=neut+((size_t)b*7+(c-17))*Dd;
    else          src=assas+(size_t)b*Dd;
    __shared__ float red[256];
    float m[3]; float loc=0.f;
#pragma unroll
    for(int i=0;i<3;i++){ m[i]=src[t+i*256]; loc+=m[i]*m[i]; }
    red[t]=loc; __syncthreads();
    for(int s=128;s>0;s>>=1){ if(t<s) red[t]+=red[t+s]; __syncthreads(); }
    float inv=1.f/fmaxf(sqrtf(red[0]),1e-12f);
#pragma unroll
    for(int i=0;i<3;i++) g_cluet[((size_t)b*768+t+i*256)*32+c]=m[i]*inv;
}

// ---------- MLP GEMM transposed: block = 64 neurons x 64 batch rows, FFMA2 ----------
__global__ void __launch_bounds__(128) gemmT_k(const float* __restrict__ X, const float* __restrict__ W,
        float* __restrict__ part, int Kdim, int Ndim, int kchunk){
    __shared__ float ws[16][68];
    __shared__ float msd[16][130];
    int tid=threadIdx.x;
    int n0=blockIdx.x*64;
    int kbeg=blockIdx.y*kchunk, kend=min(Kdim,kbeg+kchunk);
    int rg=tid&15, cg=tid>>4;
    u64t acc2[2][8];
#pragma unroll
    for(int i=0;i<2;i++)
#pragma unroll
        for(int j=0;j<8;j++) acc2[i][j]=0ull;

    float4 wr[2], xr[2];
#pragma unroll
    for(int i=0;i<2;i++){
        int q=tid+i*128; int kr=q>>4, c4=(q&15)*4;
        int k=kbeg+kr, n=n0+c4;
        float4 v=make_float4(0,0,0,0);
        if(k<kend && n<Ndim) v=*(const float4*)(W+(size_t)k*Ndim+n);
        wr[i]=v;
    }
#pragma unroll
    for(int i=0;i<2;i++){
        int q=tid+i*128; int r=q>>2, c4=(q&3)*4;
        int k=kbeg+c4;
        float4 v=make_float4(0,0,0,0);
        if(k<kend) v=*(const float4*)(X+(size_t)r*Kdim+k);
        xr[i]=v;
    }
    for(int k0=kbeg;k0<kend;k0+=16){
#pragma unroll
        for(int i=0;i<2;i++){
            int q=tid+i*128; int kr=q>>4, c4=(q&15)*4;
            *(float4*)&ws[kr][c4]=wr[i];
        }
#pragma unroll
        for(int i=0;i<2;i++){
            int q=tid+i*128; int r=q>>2, c4=(q&3)*4;
            float vv[4]={xr[i].x,xr[i].y,xr[i].z,xr[i].w};
#pragma unroll
            for(int j=0;j<4;j++){
                float2 d=make_float2(vv[j],vv[j]);
                *(float2*)&msd[c4+j][2*r]=d;
            }
        }
        __syncthreads();
        int kn=k0+16;
        if(kn<kend){
#pragma unroll
            for(int i=0;i<2;i++){
                int q=tid+i*128; int kr=q>>4, c4=(q&15)*4;
                int k=kn+kr, n=n0+c4;
                float4 v=make_float4(0,0,0,0);
                if(k<kend && n<Ndim) v=*(const float4*)(W+(size_t)k*Ndim+n);
                wr[i]=v;
            }
#pragma unroll
            for(int i=0;i<2;i++){
                int q=tid+i*128; int r=q>>2, c4=(q&3)*4;
                int k=kn+c4;
                float4 v=make_float4(0,0,0,0);
                if(k<kend) v=*(const float4*)(X+(size_t)r*Kdim+k);
                xr[i]=v;
            }
        }
#pragma unroll
        for(int kk=0;kk<16;kk++){
            const u64t* ap=(const u64t*)&ws[kk][rg*4];
            u64t a0=ap[0], a1=ap[1];
            const u64t* bp=(const u64t*)&msd[kk][cg*16];
#pragma unroll
            for(int j=0;j<8;j++){
                u64t bv=bp[j];
                acc2[0][j]=ffma2(a0,bv,acc2[0][j]);
                acc2[1][j]=ffma2(a1,bv,acc2[1][j]);
            }
        }
        __syncthreads();
    }
    float* dst=part+(size_t)blockIdx.y*Bsz*Ndim;
#pragma unroll
    for(int i=0;i<2;i++){
        int n=n0+rg*4+2*i;
#pragma unroll
        for(int j=0;j<8;j++){
            int row=cg*8+j;
            if(n<Ndim)   dst[(size_t)row*Ndim+n]  =u2lo(acc2[i][j]);
            if(n+1<Ndim) dst[(size_t)row*Ndim+n+1]=u2hi(acc2[i][j]);
        }
    }
}

__global__ void combine_act_k(const float* __restrict__ part, const float* __restrict__ bias,
                              float* __restrict__ Y, int Ndim, int S, int act){
    int idx=blockIdx.x*blockDim.x+threadIdx.x;
    int total=Bsz*Ndim;
    if(idx>=total) return;
    int c=idx%Ndim;
    float s=bias[c];
    for(int sp=0;sp<S;sp++) s+=part[(size_t)sp*total+idx];
    Y[idx]=act?tanhf(s):s;
}

__global__ void norm_mo_k(float* __restrict__ out){
    int b=blockIdx.x, t=threadIdx.x;
    __shared__ float red[256];
    float m[3]; float loc=0.f;
#pragma unroll
    for(int i=0;i<3;i++){ m[i]=g_h4[b*768+t+i*256]; loc+=m[i]*m[i]; }
    red[t]=loc; __syncthreads();
    for(int s=128;s>0;s>>=1){ if(t<s) red[t]+=red[t+s]; __syncthreads(); }
    float inv=1.f/fmaxf(sqrtf(red[0]),1e-12f);
#pragma unroll
    for(int i=0;i<3;i++){
        float v=m[i]*inv;
        int k=t+i*256;
        g_mo[b*768+k]=v;
        out[b*768+k]=v;
    }
}

// ---------- B fragments: model_out split to bf16 hi/lo in mma layout ----------
__global__ void bfrag_k(){
    int k16=blockIdx.x, nb=blockIdx.y, lane=threadIdx.x; // 32 threads
    int g=lane>>2, tq=lane&3;
    int n=nb*8+g;
    int k0=k16*16+tq*2;
    const float* B=g_mo+(size_t)n*768;
    float2 v0=make_float2(B[k0],B[k0+1]);
    float2 v1=make_float2(B[k0+8],B[k0+9]);
    unsigned h0,l0,h1,l1;
    split2(v0,h0,l0); split2(v1,h1,l1);
    g_bfh[(k16*8+nb)*32+lane]=make_uint2(h0,h1);
    g_bfl[(k16*8+nb)*32+lane]=make_uint2(l0,l1);
}

// ---------- sims: split-bf16 mma.sync, 128 rows/block, fused norm + histogram ----------
__global__ void __launch_bounds__(256) sims_mma_k(const float* __restrict__ vocab){
    int tid=threadIdx.x, w=tid>>5, lane=tid&31;
    int g=lane>>2, tq=lane&3;
    int r0=blockIdx.x*128+w*16+g, r1=r0+8;
    bool ok0=r0<VOC, ok1=r1<VOC;
    const float* p0=vocab+(size_t)r0*768;
    const float* p1=vocab+(size_t)r1*768;
    float d[8][4];
#pragma unroll
    for(int i=0;i<8;i++)
#pragma unroll
        for(int j=0;j<4;j++) d[i][j]=0.f;
    float sq0=0.f, sq1=0.f;
    for(int k16=0;k16<48;k16++){
        int kb=k16*16+tq*2;
        float2 f0=ok0?*(const float2*)(p0+kb):make_float2(0,0);
        float2 f1=ok1?*(const float2*)(p1+kb):make_float2(0,0);
        float2 f2=ok0?*(const float2*)(p0+kb+8):make_float2(0,0);
        float2 f3=ok1?*(const float2*)(p1+kb+8):make_float2(0,0);
        sq0+=f0.x*f0.x+f0.y*f0.y+f2.x*f2.x+f2.y*f2.y;
        sq1+=f1.x*f1.x+f1.y*f1.y+f3.x*f3.x+f3.y*f3.y;
        unsigned ah0,ah1,ah2,ah3, al0,al1,al2,al3;
        split2(f0,ah0,al0); split2(f1,ah1,al1);
        split2(f2,ah2,al2); split2(f3,ah3,al3);
        const uint2* bhp=g_bfh+(size_t)k16*8*32+lane;
        const uint2* blp=g_bfl+(size_t)k16*8*32+lane;
#pragma unroll
        for(int nb=0;nb<8;nb++){
            uint2 bh=bhp[nb*32];
            uint2 bl=blp[nb*32];
            MMA_BF16(d[nb],ah0,ah1,ah2,ah3,bh.x,bh.y);
            MMA_BF16(d[nb],al0,al1,al2,al3,bh.x,bh.y);
            MMA_BF16(d[nb],ah0,ah1,ah2,ah3,bl.x,bl.y);
        }
    }
    // full row sumsq: reduce across the 4 lanes sharing a row (tq dimension)
    sq0+=__shfl_xor_sync(0xffffffff,sq0,1); sq0+=__shfl_xor_sync(0xffffffff,sq0,2);
    sq1+=__shfl_xor_sync(0xffffffff,sq1,1); sq1+=__shfl_xor_sync(0xffffffff,sq1,2);
    float ri0=1.f/fmaxf(sqrtf(sq0),1e-12f);
    float ri1=1.f/fmaxf(sqrtf(sq1),1e-12f);
#pragma unroll
    for(int nb=0;nb<8;nb++){
        int n0=nb*8+tq*2;
        if(ok0){
            float s0=d[nb][0]*ri0, s1=d[nb][1]*ri0;
            g_sims[(size_t)n0*VOC+r0]=s0;
            g_sims[(size_t)(n0+1)*VOC+r0]=s1;
            atomicAdd(&g_hist[(size_t)n0*65536+(f2u(s0)>>16)],1u);
            atomicAdd(&g_hist[(size_t)(n0+1)*65536+(f2u(s1)>>16)],1u);
        }
        if(ok1){
            float s2=d[nb][2]*ri1, s3=d[nb][3]*ri1;
            g_sims[(size_t)n0*VOC+r1]=s2;
            g_sims[(size_t)(n0+1)*VOC+r1]=s3;
            atomicAdd(&g_hist[(size_t)n0*65536+(f2u(s2)>>16)],1u);
            atomicAdd(&g_hist[(size_t)(n0+1)*65536+(f2u(s3)>>16)],1u);
        }
    }
}

// ---------- top-512 ----------
__global__ void zero_hist_k(){
    int idx=blockIdx.x*blockDim.x+threadIdx.x;
    if(idx<Bsz*65536) g_hist[idx]=0u;
    if(idx<Bsz) g_cnt[idx]=0u;
}
__global__ void sel_k(){
    int b=blockIdx.x, t=threadIdx.x;  // 1024
    __shared__ unsigned ssum[1024];
    const unsigned* h=g_hist+(size_t)b*65536;
    int base=t*64;
    unsigned s=0;
    for(int i=0;i<64;i++) s+=h[base+i];
    ssum[t]=s; __syncthreads();
    unsigned above=0;
    for(int j=t+1;j<1024;j++) above+=ssum[j];
    if(above<512u && above+s>=512u){
        unsigned run=above;
        for(int i=63;i>=0;i--){
            unsigned hv=h[base+i];
            if(run+hv>=512u){ g_thr[b]=base+i; break; }
            run+=hv;
        }
    }
}
__global__ void collect_k(){
    int b=blockIdx.y, t=threadIdx.x;
    int start=blockIdx.x*12500, end=start+12500;
    unsigned binb=(unsigned)g_thr[b];
    const float* srow=g_sims+(size_t)b*VOC;
    for(int v=start+t;v<end;v+=512){
        unsigned u=f2u(srow[v]);
        if((u>>16)>=binb){
            unsigned pos=atomicAdd(&g_cnt[b],1u);
            if(pos<4096u) g_cand[(size_t)b*4096+pos]=((u64t)(~u)<<32)|(unsigned)v;
        }
    }
}
__global__ void final_sel_k(){
    int b=blockIdx.x, t=threadIdx.x;  // 512
    __shared__ u64t cand[4096];
    __shared__ u64t outk[512];
    int m=min(g_cnt[b],4096u);
    for(int i=t;i<m;i+=512) cand[i]=g_cand[(size_t)b*4096+i];
    __syncthreads();
    for(int i=t;i<m;i+=512){
        u64t key=cand[i]; int rank=0;
        for(int j=0;j<m;j++) rank+=(cand[j]<key);
        if(rank<512) outk[rank]=key;
    }
    __syncthreads();
    g_topidx[b*512+t]=(int)(outk[t]&0xffffffffu);
}

// ---------- gathered clue GEMM + primary/secondary ----------
__global__ void combined_k(const float* __restrict__ vocab){
    __shared__ float ws[32][64];
    __shared__ float cs[32][32];
    __shared__ int sidx[64];
    __shared__ float outc[64][32];
    int b=blockIdx.y, w0=blockIdx.x*64, tid=threadIdx.x; // 256
    if(tid<64) sidx[tid]=g_topidx[b*512+w0+tid];
    __syncthreads();
    int c=tid&31, w8=tid>>5;
    float acc[8];
#pragma unroll
    for(int i=0;i<8;i++) acc[i]=0.f;
    for(int k0=0;k0<768;k0+=32){
#pragma unroll
        for(int i=0;i<2;i++){
            int q=tid+i*256, r=q>>3, c4=(q&7)*4;
            float4 v=*(const float4*)(vocab+(size_t)sidx[r]*768+k0+c4);
            ws[c4+0][r]=v.x; ws[c4+1][r]=v.y; ws[c4+2][r]=v.z; ws[c4+3][r]=v.w;
        }
#pragma unroll
        for(int i=0;i<4;i++){
            int q=tid+i*256, kk=q>>5, cc=q&31;
            cs[kk][cc]=(cc<25)?g_cluet[((size_t)b*768+k0+kk)*32+cc]:0.f;
        }
        __syncthreads();
#pragma unroll
        for(int kk=0;kk<32;kk++){
            float cv=cs[kk][c];
            float4 a0=*(const float4*)&ws[kk][w8*8];
            float4 a1=*(const float4*)&ws[kk][w8*8+4];
            acc[0]+=a0.x*cv; acc[1]+=a0.y*cv; acc[2]+=a0.z*cv; acc[3]+=a0.w*cv;
            acc[4]+=a1.x*cv; acc[5]+=a1.y*cv; acc[6]+=a1.z*cv; acc[7]+=a1.w*cv;
        }
        __syncthreads();
    }
#pragma unroll
    for(int i=0;i<8;i++) outc[w8*8+i][c]=acc[i];
    __syncthreads();
    if(tid<64){
        float* row=outc[tid];
        float mbest=-1e30f; int jbest=9;
        for(int j=9;j<25;j++){ float v=row[j]; if(v>mbest){mbest=v; jbest=j;} }
        int primary=0;
        for(int p=0;p<9;p++) primary+=(row[p]>=mbest);
        float sec=(jbest<17)?0.f:((jbest<24)?1.f:-10.f);
        g_tot[b*512+w0+tid]=(float)primary+sec;
    }
}

// ---------- rank ----------
__global__ void rank_k(){
    int b=blockIdx.x, t=threadIdx.x; // 512
    __shared__ float tv[512];
    tv[t]=g_tot[b*512+t]; __syncthreads();
    float mv=tv[t]; int gt=0, lt=0, eqb=0;
    for(int j=0;j<512;j++){
        float o=tv[j];
        gt+=(o>mv); lt+=(o<mv); eqb+=((o==mv)&&(j<t));
    }
    int rmax=gt+eqb, rmin=lt+eqb;
    g_flags[b*512+t]=((rmax<256)?1:0)|((rmin<256)?2:0);
    if(rmax==0) g_search[b]=g_topidx[b*512+t];
}

// ---------- final pooled outputs ----------
__global__ void final_acc_k(const float* __restrict__ vocab){
    int b=blockIdx.y, c=blockIdx.x, t=threadIdx.x; // 256
    const int* ti=g_topidx+b*512+c*64;
    const int* fl=g_flags+b*512+c*64;
    float amax[3]={0,0,0}, amin[3]={0,0,0};
    for(int w=0;w<64;w++){
        int f=fl[w];
        if(f){
            const float* row=vocab+(size_t)ti[w]*768;
#pragma unroll
            for(int i=0;i<3;i++){
                float v=row[t+i*256];
                if(f&1) amax[i]+=v;
                if(f&2) amin[i]+=v;
            }
        }
    }
    float* pp=g_pp+(size_t)(b*8+c)*2*768;
#pragma unroll
    for(int i=0;i<3;i++){
        pp[t+i*256]=amax[i];
        pp[768+t+i*256]=amin[i];
    }
}
__global__ void final_red_k(const float* __restrict__ vocab, float* __restrict__ out){
    int b=blockIdx.x, t=threadIdx.x; // 256
    __shared__ float red[256];
    float amax[3]={0,0,0}, amin[3]={0,0,0};
    for(int c=0;c<8;c++){
        const float* pp=g_pp+(size_t)(b*8+c)*2*768;
#pragma unroll
        for(int i=0;i<3;i++){
            amax[i]+=pp[t+i*256];
            amin[i]+=pp[768+t+i*256];
        }
    }
    float loc=0.f;
#pragma unroll
    for(int i=0;i<3;i++){ amax[i]*=(1.f/256.f); loc+=amax[i]*amax[i]; }
    red[t]=loc; __syncthreads();
    for(int s=128;s>0;s>>=1){ if(t<s) red[t]+=red[t+s]; __syncthreads(); }
    float inv=1.f/fmaxf(sqrtf(red[0]),1e-12f);
#pragma unroll
    for(int i=0;i<3;i++) out[2*49152+b*768+t+i*256]=amax[i]*inv;
    __syncthreads();
    loc=0.f;
#pragma unroll
    for(int i=0;i<3;i++){ amin[i]*=(1.f/256.f); loc+=amin[i]*amin[i]; }
    red[t]=loc; __syncthreads();
    for(int s=128;s>0;s>>=1){ if(t<s) red[t]+=red[t+s]; __syncthreads(); }
    inv=1.f/fmaxf(sqrtf(red[0]),1e-12f);
#pragma unroll
    for(int i=0;i<3;i++) out[3*49152+b*768+t+i*256]=amin[i]*inv;
    int sw=g_search[b];
#pragma unroll
    for(int i=0;i<3;i++) out[49152+b*768+t+i*256]=vocab[(size_t)sw*768+t+i*256];
}

extern "C" void kernel_launch(void* const* d_in, const int* in_sizes, int n_in,
                              void* d_out, int out_size){
    const float* pos  =(const float*)d_in[0];
    const float* neg  =(const float*)d_in[1];
    const float* neut =(const float*)d_in[2];
    const float* assas=(const float*)d_in[3];
    const float* vocab=(const float*)d_in[4];
    const float* W1=(const float*)d_in[5];  const float* b1=(const float*)d_in[6];
    const float* W2=(const float*)d_in[7];  const float* b2=(const float*)d_in[8];
    const float* W3=(const float*)d_in[9];  const float* b3=(const float*)d_in[10];
    const float* W4=(const float*)d_in[11]; const float* b4=(const float*)d_in[12];
    float* out=(float*)d_out;

    float *gx, *gh1, *gh2, *gh3, *gh4, *gpart;
    cudaGetSymbolAddress((void**)&gx,   g_x);
    cudaGetSymbolAddress((void**)&gh1,  g_h1);
    cudaGetSymbolAddress((void**)&gh2,  g_h2);
    cudaGetSymbolAddress((void**)&gh3,  g_h3);
    cudaGetSymbolAddress((void**)&gh4,  g_h4);
    cudaGetSymbolAddress((void**)&gpart,g_part);

    zero_hist_k<<<(Bsz*65536+1023)/1024,1024>>>();
    pool_concat_k<<<dim3(4,64),256>>>(pos,neg,neut,assas);
    clue_norm_k<<<dim3(25,64),256>>>(pos,neg,neut,assas);

    // L1: K=3072 N=2304, 36 ntiles x 24 splits (kchunk 128)
    gemmT_k<<<dim3(36,24),128>>>(gx,W1,gpart,3072,2304,128);
    combine_act_k<<<(64*2304+255)/256,256>>>(gpart,b1,gh1,2304,24,1);
    // L2: K=2304 N=1700, 27 x 18 (kchunk 128)
    gemmT_k<<<dim3(27,18),128>>>(gh1,W2,gpart,2304,1700,128);
    combine_act_k<<<(64*1700+255)/256,256>>>(gpart,b2,gh2,1700,18,1);
    // L3: K=1700 N=1000, 16 x 27 (kchunk 64)
    gemmT_k<<<dim3(16,27),128>>>(gh2,W3,gpart,1700,1000,64);
    combine_act_k<<<(64*1000+255)/256,256>>>(gpart,b3,gh3,1000,27,1);
    // L4: K=1000 N=768, 12 x 32 (kchunk 32)
    gemmT_k<<<dim3(12,32),128>>>(gh3,W4,gpart,1000,768,32);
    combine_act_k<<<(64*768+255)/256,256>>>(gpart,b4,gh4,768,32,0);

    norm_mo_k<<<64,256>>>(out);
    bfrag_k<<<dim3(48,8),32>>>();
    sims_mma_k<<<(VOC+127)/128,256>>>(vocab);

    sel_k<<<64,1024>>>();
    collect_k<<<dim3(8,64),512>>>();
    final_sel_k<<<64,512>>>();

    combined_k<<<dim3(8,64),256>>>(vocab);
    rank_k<<<64,512>>>();
    final_acc_k<<<dim3(8,64),256>>>(vocab);
    final_red_k<<<64,256>>>(vocab,out);
}

// round 6
// speedup vs baseline: 1.7270x; 1.1000x over previous
#include <cuda_runtime.h>
#include <cuda_bf16.h>
#include <math.h>
#include <stdint.h>

#define Bsz 64
#define Dd  768
#define VOC 100000
#define KTOP 512

typedef unsigned long long u64t;

// ---------- scratch ----------
__device__ float g_x [Bsz*3072];
__device__ float g_h1[Bsz*2304];
__device__ float g_h2[Bsz*1700];
__device__ float g_h3[Bsz*1000];
__device__ float g_h4[Bsz*768];
__device__ float g_mo[Bsz*768];
__device__ uint2 g_bfh[48*8*32];
__device__ uint2 g_bfl[48*8*32];
__device__ float g_cluet[Bsz*768*32];          // cols 25..31 never written -> zero
__device__ float g_sims[(size_t)Bsz*VOC];
__device__ unsigned g_hist[Bsz*65536];
__device__ int      g_thr[Bsz];
__device__ unsigned g_cnt[Bsz];
__device__ u64t     g_cand[Bsz*4096];
__device__ int   g_topidx[Bsz*KTOP];
__device__ float g_tot[Bsz*KTOP];
__device__ int   g_flags[Bsz*KTOP];
__device__ int   g_search[Bsz];
__device__ float g_part[3538944];
__device__ float g_pp[Bsz*8*2*768];

__device__ __forceinline__ unsigned f2u(float f){
    unsigned u = __float_as_uint(f);
    return (u & 0x80000000u) ? ~u : (u | 0x80000000u);
}
__device__ __forceinline__ u64t ffma2(u64t a, u64t b, u64t c){
    u64t d;
    asm("fma.rn.f32x2 %0, %1, %2, %3;" : "=l"(d) : "l"(a), "l"(b), "l"(c));
    return d;
}
__device__ __forceinline__ float u2lo(u64t v){ return __uint_as_float((unsigned)v); }
__device__ __forceinline__ float u2hi(u64t v){ return __uint_as_float((unsigned)(v>>32)); }

// fast split: f32x2 -> packed bf16x2 hi + lo (RN, matches __float2bfloat16)
__device__ __forceinline__ void fsplit2(float2 f, unsigned &hi, unsigned &lo){
    unsigned h;
    asm("cvt.rn.bf16x2.f32 %0, %1, %2;" : "=r"(h) : "f"(f.y), "f"(f.x));
    float h0=__uint_as_float(h<<16);
    float h1=__uint_as_float(h&0xffff0000u);
    float l0=f.x-h0, l1=f.y-h1;
    asm("cvt.rn.bf16x2.f32 %0, %1, %2;" : "=r"(lo) : "f"(l1), "f"(l0));
    hi=h;
}

#define MMA_BF16(D,A0,A1,A2,A3,B0,B1) \
  asm volatile("mma.sync.aligned.m16n8k16.row.col.f32.bf16.bf16.f32 " \
    "{%0,%1,%2,%3},{%4,%5,%6,%7},{%8,%9},{%0,%1,%2,%3};" \
    : "+f"(D[0]),"+f"(D[1]),"+f"(D[2]),"+f"(D[3]) \
    : "r"(A0),"r"(A1),"r"(A2),"r"(A3),"r"(B0),"r"(B1))

// ---------- stage 1 ----------
__global__ void pool_concat_k(const float* __restrict__ pos, const float* __restrict__ neg,
                              const float* __restrict__ neut, const float* __restrict__ assas){
    int b=blockIdx.y, g=blockIdx.x, t=threadIdx.x;
    __shared__ float red[256];
    const float* src; int n, xoff;
    if(g==0){src=neg +(size_t)b*8*Dd; n=8; xoff=0;}
    else if(g==1){src=assas+(size_t)b*Dd; n=1; xoff=Dd;}
    else if(g==2){src=neut+(size_t)b*7*Dd; n=7; xoff=2*Dd;}
    else {src=pos +(size_t)b*9*Dd; n=9; xoff=3*Dd;}
    float m[3];
#pragma unroll
    for(int i=0;i<3;i++){int d=t+i*256; float s=0.f;
        for(int j=0;j<n;j++) s+=src[(size_t)j*Dd+d]; m[i]=s/(float)n;}
    if(g==1){
#pragma unroll
        for(int i=0;i<3;i++) g_x[b*3072+xoff+t+i*256]=m[i];
        return;
    }
    red[t]=m[0]*m[0]+m[1]*m[1]+m[2]*m[2]; __syncthreads();
    for(int s=128;s>0;s>>=1){ if(t<s) red[t]+=red[t+s]; __syncthreads(); }
    float inv=1.f/fmaxf(sqrtf(red[0]),1e-12f);
#pragma unroll
    for(int i=0;i<3;i++) g_x[b*3072+xoff+t+i*256]=m[i]*inv;
}

__global__ void clue_norm_k(const float* __restrict__ pos, const float* __restrict__ neg,
                            const float* __restrict__ neut, const float* __restrict__ assas){
    int c=blockIdx.x, b=blockIdx.y, t=threadIdx.x;
    const float* src;
    if(c<9)       src=pos +((size_t)b*9+c)*Dd;
    else if(c<17) src=neg +((size_t)b*8+(c-9))*Dd;
    else if(c<24) src=neut+((size_t)b*7+(c-17))*Dd;
    else          src=assas+(size_t)b*Dd;
    __shared__ float red[256];
    float m[3]; float loc=0.f;
#pragma unroll
    for(int i=0;i<3;i++){ m[i]=src[t+i*256]; loc+=m[i]*m[i]; }
    red[t]=loc; __syncthreads();
    for(int s=128;s>0;s>>=1){ if(t<s) red[t]+=red[t+s]; __syncthreads(); }
    float inv=1.f/fmaxf(sqrtf(red[0]),1e-12f);
#pragma unroll
    for(int i=0;i<3;i++) g_cluet[((size_t)b*768+t+i*256)*32+c]=m[i]*inv;
}

// ---------- MLP GEMM: 256 threads, tile 128 neurons x 64 rows, FFMA2 ----------
__global__ void __launch_bounds__(256) gemmT_k(const float* __restrict__ X, const float* __restrict__ W,
        float* __restrict__ part, int Kdim, int Ndim, int kchunk){
    __shared__ float ws[16][132];
    __shared__ float msd[16][132];
    int tid=threadIdx.x;
    int n0=blockIdx.x*128;
    int kbeg=blockIdx.y*kchunk, kend=min(Kdim,kbeg+kchunk);
    int rg=tid&31, cg=tid>>5;
    u64t acc2[2][8];
#pragma unroll
    for(int i=0;i<2;i++)
#pragma unroll
        for(int j=0;j<8;j++) acc2[i][j]=0ull;

    float4 wr[2], xr;
#pragma unroll
    for(int i=0;i<2;i++){
        int q=tid+i*256; int kr=q>>5, c4=(q&31)*4;
        int k=kbeg+kr, n=n0+c4;
        float4 v=make_float4(0,0,0,0);
        if(k<kend && n<Ndim) v=*(const float4*)(W+(size_t)k*Ndim+n);
        wr[i]=v;
    }
    {
        int r=tid>>2, c4=(tid&3)*4;
        int k=kbeg+c4;
        xr=make_float4(0,0,0,0);
        if(k<kend) xr=*(const float4*)(X+(size_t)r*Kdim+k);
    }
    for(int k0=kbeg;k0<kend;k0+=16){
#pragma unroll
        for(int i=0;i<2;i++){
            int q=tid+i*256; int kr=q>>5, c4=(q&31)*4;
            *(float4*)&ws[kr][c4]=wr[i];
        }
        {
            int r=tid>>2, c4=(tid&3)*4;
            float vv[4]={xr.x,xr.y,xr.z,xr.w};
#pragma unroll
            for(int j=0;j<4;j++)
                *(float2*)&msd[c4+j][2*r]=make_float2(vv[j],vv[j]);
        }
        __syncthreads();
        int kn=k0+16;
        if(kn<kend){
#pragma unroll
            for(int i=0;i<2;i++){
                int q=tid+i*256; int kr=q>>5, c4=(q&31)*4;
                int k=kn+kr, n=n0+c4;
                float4 v=make_float4(0,0,0,0);
                if(k<kend && n<Ndim) v=*(const float4*)(W+(size_t)k*Ndim+n);
                wr[i]=v;
            }
            {
                int r=tid>>2, c4=(tid&3)*4;
                int k=kn+c4;
                xr=make_float4(0,0,0,0);
                if(k<kend) xr=*(const float4*)(X+(size_t)r*Kdim+k);
            }
        }
#pragma unroll
        for(int kk=0;kk<16;kk++){
            const u64t* ap=(const u64t*)&ws[kk][rg*4];
            u64t a0=ap[0], a1=ap[1];
            const u64t* bp=(const u64t*)&msd[kk][cg*16];
#pragma unroll
            for(int j=0;j<8;j++){
                u64t bv=bp[j];
                acc2[0][j]=ffma2(a0,bv,acc2[0][j]);
                acc2[1][j]=ffma2(a1,bv,acc2[1][j]);
            }
        }
        __syncthreads();
    }
    float* dst=part+(size_t)blockIdx.y*Bsz*Ndim;
#pragma unroll
    for(int i=0;i<2;i++){
        int n=n0+rg*4+2*i;
#pragma unroll
        for(int j=0;j<8;j++){
            int row=cg*8+j;
            if(n<Ndim)   dst[(size_t)row*Ndim+n]  =u2lo(acc2[i][j]);
            if(n+1<Ndim) dst[(size_t)row*Ndim+n+1]=u2hi(acc2[i][j]);
        }
    }
}

__global__ void combine_act_k(const float* __restrict__ part, const float* __restrict__ bias,
                              float* __restrict__ Y, int Ndim, int S, int act){
    int idx=blockIdx.x*blockDim.x+threadIdx.x;
    int total=Bsz*Ndim;
    if(idx>=total) return;
    int c=idx%Ndim;
    float s=bias[c];
    for(int sp=0;sp<S;sp++) s+=part[(size_t)sp*total+idx];
    Y[idx]=act?tanhf(s):s;
}

__global__ void norm_mo_k(float* __restrict__ out){
    int b=blockIdx.x, t=threadIdx.x;
    __shared__ float red[256];
    float m[3]; float loc=0.f;
#pragma unroll
    for(int i=0;i<3;i++){ m[i]=g_h4[b*768+t+i*256]; loc+=m[i]*m[i]; }
    red[t]=loc; __syncthreads();
    for(int s=128;s>0;s>>=1){ if(t<s) red[t]+=red[t+s]; __syncthreads(); }
    float inv=1.f/fmaxf(sqrtf(red[0]),1e-12f);
#pragma unroll
    for(int i=0;i<3;i++){
        float v=m[i]*inv;
        int k=t+i*256;
        g_mo[b*768+k]=v;
        out[b*768+k]=v;
    }
}

// ---------- B fragments ----------
__global__ void bfrag_k(){
    int k16=blockIdx.x, nb=blockIdx.y, lane=threadIdx.x;
    int g=lane>>2, tq=lane&3;
    int n=nb*8+g;
    int k0=k16*16+tq*2;
    const float* B=g_mo+(size_t)n*768;
    float2 v0=make_float2(B[k0],B[k0+1]);
    float2 v1=make_float2(B[k0+8],B[k0+9]);
    unsigned h0,l0,h1,l1;
    fsplit2(v0,h0,l0); fsplit2(v1,h1,l1);
    g_bfh[(k16*8+nb)*32+lane]=make_uint2(h0,h1);
    g_bfl[(k16*8+nb)*32+lane]=make_uint2(l0,l1);
}

// ---------- sims: split-bf16 mma, 2 m-tiles/warp (32 rows), fused norm+hist ----------
__global__ void __launch_bounds__(256) sims_mma_k(const float* __restrict__ vocab){
    int tid=threadIdx.x, w=tid>>5, lane=tid&31;
    int g=lane>>2, tq=lane&3;
    int base=blockIdx.x*256 + w*32;
    int r[4]={base+g, base+8+g, base+16+g, base+24+g};
    bool ok[4];
    const float* p[4];
#pragma unroll
    for(int i=0;i<4;i++){ ok[i]=r[i]<VOC; p[i]=vocab+(size_t)r[i]*768; }
    float d[2][8][4];
#pragma unroll
    for(int t=0;t<2;t++)
#pragma unroll
        for(int i=0;i<8;i++)
#pragma unroll
            for(int j=0;j<4;j++) d[t][i][j]=0.f;
    float sq[4]={0,0,0,0};
    for(int k16=0;k16<48;k16++){
        int kb=k16*16+tq*2;
        float2 f[4][2];
#pragma unroll
        for(int i=0;i<4;i++){
            f[i][0]=ok[i]?*(const float2*)(p[i]+kb):make_float2(0,0);
            f[i][1]=ok[i]?*(const float2*)(p[i]+kb+8):make_float2(0,0);
            sq[i]+=f[i][0].x*f[i][0].x+f[i][0].y*f[i][0].y
                  +f[i][1].x*f[i][1].x+f[i][1].y*f[i][1].y;
        }
        unsigned ah[4][2], al[4][2];
#pragma unroll
        for(int i=0;i<4;i++){
            fsplit2(f[i][0],ah[i][0],al[i][0]);
            fsplit2(f[i][1],ah[i][1],al[i][1]);
        }
        const uint2* bhp=g_bfh+(size_t)k16*8*32+lane;
        const uint2* blp=g_bfl+(size_t)k16*8*32+lane;
#pragma unroll
        for(int nb=0;nb<8;nb++){
            uint2 bh=bhp[nb*32];
            uint2 bl=blp[nb*32];
            // tile 0: rows r[0], r[1]
            MMA_BF16(d[0][nb],ah[0][0],ah[1][0],ah[0][1],ah[1][1],bh.x,bh.y);
            MMA_BF16(d[0][nb],al[0][0],al[1][0],al[0][1],al[1][1],bh.x,bh.y);
            MMA_BF16(d[0][nb],ah[0][0],ah[1][0],ah[0][1],ah[1][1],bl.x,bl.y);
            // tile 1: rows r[2], r[3]
            MMA_BF16(d[1][nb],ah[2][0],ah[3][0],ah[2][1],ah[3][1],bh.x,bh.y);
            MMA_BF16(d[1][nb],al[2][0],al[3][0],al[2][1],al[3][1],bh.x,bh.y);
            MMA_BF16(d[1][nb],ah[2][0],ah[3][0],ah[2][1],ah[3][1],bl.x,bl.y);
        }
    }
    float ri[4];
#pragma unroll
    for(int i=0;i<4;i++){
        sq[i]+=__shfl_xor_sync(0xffffffff,sq[i],1);
        sq[i]+=__shfl_xor_sync(0xffffffff,sq[i],2);
        ri[i]=1.f/fmaxf(sqrtf(sq[i]),1e-12f);
    }
#pragma unroll
    for(int t=0;t<2;t++){
#pragma unroll
        for(int nb=0;nb<8;nb++){
            int n0=nb*8+tq*2;
            if(ok[2*t]){
                float s0=d[t][nb][0]*ri[2*t], s1=d[t][nb][1]*ri[2*t];
                g_sims[(size_t)n0*VOC+r[2*t]]=s0;
                g_sims[(size_t)(n0+1)*VOC+r[2*t]]=s1;
                atomicAdd(&g_hist[(size_t)n0*65536+(f2u(s0)>>16)],1u);
                atomicAdd(&g_hist[(size_t)(n0+1)*65536+(f2u(s1)>>16)],1u);
            }
            if(ok[2*t+1]){
                float s2=d[t][nb][2]*ri[2*t+1], s3=d[t][nb][3]*ri[2*t+1];
                g_sims[(size_t)n0*VOC+r[2*t+1]]=s2;
                g_sims[(size_t)(n0+1)*VOC+r[2*t+1]]=s3;
                atomicAdd(&g_hist[(size_t)n0*65536+(f2u(s2)>>16)],1u);
                atomicAdd(&g_hist[(size_t)(n0+1)*65536+(f2u(s3)>>16)],1u);
            }
        }
    }
}

// ---------- top-512 ----------
__global__ void zero_hist_k(){
    int idx=blockIdx.x*blockDim.x+threadIdx.x;
    if(idx<Bsz*65536) g_hist[idx]=0u;
    if(idx<Bsz) g_cnt[idx]=0u;
}
__global__ void sel_k(){
    int b=blockIdx.x, t=threadIdx.x;  // 1024
    __shared__ unsigned ssum[1024];
    const unsigned* h=g_hist+(size_t)b*65536;
    int base=t*64;
    unsigned s=0;
    for(int i=0;i<64;i++) s+=h[base+i];
    ssum[t]=s; __syncthreads();
    unsigned above=0;
    for(int j=t+1;j<1024;j++) above+=ssum[j];
    if(above<512u && above+s>=512u){
        unsigned run=above;
        for(int i=63;i>=0;i--){
            unsigned hv=h[base+i];
            if(run+hv>=512u){ g_thr[b]=base+i; break; }
            run+=hv;
        }
    }
}
__global__ void collect_k(){
    int b=blockIdx.y, t=threadIdx.x;
    int start=blockIdx.x*12500, end=start+12500;
    unsigned binb=(unsigned)g_thr[b];
    const float* srow=g_sims+(size_t)b*VOC;
    for(int v=start+t;v<end;v+=512){
        unsigned u=f2u(srow[v]);
        if((u>>16)>=binb){
            unsigned pos=atomicAdd(&g_cnt[b],1u);
            if(pos<4096u) g_cand[(size_t)b*4096+pos]=((u64t)(~u)<<32)|(unsigned)v;
        }
    }
}
__global__ void final_sel_k(){
    int b=blockIdx.x, t=threadIdx.x;  // 512
    __shared__ u64t cand[4096];
    __shared__ u64t outk[512];
    int m=min(g_cnt[b],4096u);
    for(int i=t;i<m;i+=512) cand[i]=g_cand[(size_t)b*4096+i];
    __syncthreads();
    for(int i=t;i<m;i+=512){
        u64t key=cand[i]; int rank=0;
        for(int j=0;j<m;j++) rank+=(cand[j]<key);
        if(rank<512) outk[rank]=key;
    }
    __syncthreads();
    g_topidx[b*512+t]=(int)(outk[t]&0xffffffffu);
}

// ---------- gathered clue GEMM (FFMA2) + primary/secondary ----------
__global__ void __launch_bounds__(128) combined_k(const float* __restrict__ vocab){
    __shared__ float wsd[16][132];   // duplicated word vals [kk][2w]
    __shared__ float cs[16][32];     // clue pairs [kk][c]
    __shared__ int sidx[64];
    __shared__ float outc[64][32];
    int b=blockIdx.y, w0=blockIdx.x*64, tid=threadIdx.x; // 128
    if(tid<64) sidx[tid]=g_topidx[b*512+w0+tid];
    __syncthreads();
    int c2=tid&15, g=tid>>4;          // 16 u64 clue-cols x 8 word groups
    u64t acc2[8];
#pragma unroll
    for(int i=0;i<8;i++) acc2[i]=0ull;
    for(int k0=0;k0<768;k0+=16){
#pragma unroll
        for(int i=0;i<2;i++){
            int q=tid+i*128, r=q>>2, c4=(q&3)*4;
            float4 v=*(const float4*)(vocab+(size_t)sidx[r]*768+k0+c4);
            float vv[4]={v.x,v.y,v.z,v.w};
#pragma unroll
            for(int j=0;j<4;j++)
                *(float2*)&wsd[c4+j][2*r]=make_float2(vv[j],vv[j]);
        }
        {   // clue tile: 16kk x 32c = 128 float4, 1 per thread
            int kk=tid>>3, cc4=(tid&7)*4;
            *(float4*)&cs[kk][cc4]=*(const float4*)(g_cluet+((size_t)b*768+k0+kk)*32+cc4);
        }
        __syncthreads();
#pragma unroll
        for(int kk=0;kk<16;kk++){
            u64t cv=*(const u64t*)&cs[kk][c2*2];
            const u64t* bp=(const u64t*)&wsd[kk][g*16];
#pragma unroll
            for(int j=0;j<8;j++)
                acc2[j]=ffma2(bp[j],cv,acc2[j]);
        }
        __syncthreads();
    }
#pragma unroll
    for(int j=0;j<8;j++){
        outc[g*8+j][2*c2]  =u2lo(acc2[j]);
        outc[g*8+j][2*c2+1]=u2hi(acc2[j]);
    }
    __syncthreads();
    if(tid<64){
        float* row=outc[tid];
        float mbest=-1e30f; int jbest=9;
        for(int j=9;j<25;j++){ float v=row[j]; if(v>mbest){mbest=v; jbest=j;} }
        int primary=0;
        for(int p=0;p<9;p++) primary+=(row[p]>=mbest);
        float sec=(jbest<17)?0.f:((jbest<24)?1.f:-10.f);
        g_tot[b*512+w0+tid]=(float)primary+sec;
    }
}

// ---------- rank ----------
__global__ void rank_k(){
    int b=blockIdx.x, t=threadIdx.x; // 512
    __shared__ float tv[512];
    tv[t]=g_tot[b*512+t]; __syncthreads();
    float mv=tv[t]; int gt=0, lt=0, eqb=0;
    for(int j=0;j<512;j++){
        float o=tv[j];
        gt+=(o>mv); lt+=(o<mv); eqb+=((o==mv)&&(j<t));
    }
    int rmax=gt+eqb, rmin=lt+eqb;
    g_flags[b*512+t]=((rmax<256)?1:0)|((rmin<256)?2:0);
    if(rmax==0) g_search[b]=g_topidx[b*512+t];
}

// ---------- final pooled outputs ----------
__global__ void final_acc_k(const float* __restrict__ vocab){
    int b=blockIdx.y, c=blockIdx.x, t=threadIdx.x; // 256
    const int* ti=g_topidx+b*512+c*64;
    const int* fl=g_flags+b*512+c*64;
    float amax[3]={0,0,0}, amin[3]={0,0,0};
    for(int w=0;w<64;w++){
        int f=fl[w];
        if(f){
            const float* row=vocab+(size_t)ti[w]*768;
#pragma unroll
            for(int i=0;i<3;i++){
                float v=row[t+i*256];
                if(f&1) amax[i]+=v;
                if(f&2) amin[i]+=v;
            }
        }
    }
    float* pp=g_pp+(size_t)(b*8+c)*2*768;
#pragma unroll
    for(int i=0;i<3;i++){
        pp[t+i*256]=amax[i];
        pp[768+t+i*256]=amin[i];
    }
}
__global__ void final_red_k(const float* __restrict__ vocab, float* __restrict__ out){
    int b=blockIdx.x, t=threadIdx.x; // 256
    __shared__ float red[256];
    float amax[3]={0,0,0}, amin[3]={0,0,0};
    for(int c=0;c<8;c++){
        const float* pp=g_pp+(size_t)(b*8+c)*2*768;
#pragma unroll
        for(int i=0;i<3;i++){
            amax[i]+=pp[t+i*256];
            amin[i]+=pp[768+t+i*256];
        }
    }
    float loc=0.f;
#pragma unroll
    for(int i=0;i<3;i++){ amax[i]*=(1.f/256.f); loc+=amax[i]*amax[i]; }
    red[t]=loc; __syncthreads();
    for(int s=128;s>0;s>>=1){ if(t<s) red[t]+=red[t+s]; __syncthreads(); }
    float inv=1.f/fmaxf(sqrtf(red[0]),1e-12f);
#pragma unroll
    for(int i=0;i<3;i++) out[2*49152+b*768+t+i*256]=amax[i]*inv;
    __syncthreads();
    loc=0.f;
#pragma unroll
    for(int i=0;i<3;i++){ amin[i]*=(1.f/256.f); loc+=amin[i]*amin[i]; }
    red[t]=loc; __syncthreads();
    for(int s=128;s>0;s>>=1){ if(t<s) red[t]+=red[t+s]; __syncthreads(); }
    inv=1.f/fmaxf(sqrtf(red[0]),1e-12f);
#pragma unroll
    for(int i=0;i<3;i++) out[3*49152+b*768+t+i*256]=amin[i]*inv;
    int sw=g_search[b];
#pragma unroll
    for(int i=0;i<3;i++) out[49152+b*768+t+i*256]=vocab[(size_t)sw*768+t+i*256];
}

extern "C" void kernel_launch(void* const* d_in, const int* in_sizes, int n_in,
                              void* d_out, int out_size){
    const float* pos  =(const float*)d_in[0];
    const float* neg  =(const float*)d_in[1];
    const float* neut =(const float*)d_in[2];
    const float* assas=(const float*)d_in[3];
    const float* vocab=(const float*)d_in[4];
    const float* W1=(const float*)d_in[5];  const float* b1=(const float*)d_in[6];
    const float* W2=(const float*)d_in[7];  const float* b2=(const float*)d_in[8];
    const float* W3=(const float*)d_in[9];  const float* b3=(const float*)d_in[10];
    const float* W4=(const float*)d_in[11]; const float* b4=(const float*)d_in[12];
    float* out=(float*)d_out;

    float *gx, *gh1, *gh2, *gh3, *gh4, *gpart;
    cudaGetSymbolAddress((void**)&gx,   g_x);
    cudaGetSymbolAddress((void**)&gh1,  g_h1);
    cudaGetSymbolAddress((void**)&gh2,  g_h2);
    cudaGetSymbolAddress((void**)&gh3,  g_h3);
    cudaGetSymbolAddress((void**)&gh4,  g_h4);
    cudaGetSymbolAddress((void**)&gpart,g_part);

    zero_hist_k<<<(Bsz*65536+1023)/1024,1024>>>();
    pool_concat_k<<<dim3(4,64),256>>>(pos,neg,neut,assas);
    clue_norm_k<<<dim3(25,64),256>>>(pos,neg,neut,assas);

    // L1: K=3072 N=2304, 18 ntiles x 24 splits (kchunk 128)
    gemmT_k<<<dim3(18,24),256>>>(gx,W1,gpart,3072,2304,128);
    combine_act_k<<<(64*2304+255)/256,256>>>(gpart,b1,gh1,2304,24,1);
    // L2: K=2304 N=1700, 14 x 18 (kchunk 128)
    gemmT_k<<<dim3(14,18),256>>>(gh1,W2,gpart,2304,1700,128);
    combine_act_k<<<(64*1700+255)/256,256>>>(gpart,b2,gh2,1700,18,1);
    // L3: K=1700 N=1000, 8 x 27 (kchunk 64)
    gemmT_k<<<dim3(8,27),256>>>(gh2,W3,gpart,1700,1000,64);
    combine_act_k<<<(64*1000+255)/256,256>>>(gpart,b3,gh3,1000,27,1);
    // L4: K=1000 N=768, 6 x 32 (kchunk 32)
    gemmT_k<<<dim3(6,32),256>>>(gh3,W4,gpart,1000,768,32);
    combine_act_k<<<(64*768+255)/256,256>>>(gpart,b4,gh4,768,32,0);

    norm_mo_k<<<64,256>>>(out);
    bfrag_k<<<dim3(48,8),32>>>();
    sims_mma_k<<<(VOC+255)/256,256>>>(vocab);

    sel_k<<<64,1024>>>();
    collect_k<<<dim3(8,64),512>>>();
    final_sel_k<<<64,512>>>();

    combined_k<<<dim3(8,64),128>>>(vocab);
    rank_k<<<64,512>>>();
    final_acc_k<<<dim3(8,64),256>>>(vocab);
    final_red_k<<<64,256>>>(vocab,out);
}